// round 3
// baseline (speedup 1.0000x reference)
#include <cuda_runtime.h>
#include <math.h>

#define B_   32
#define N_   196
#define C_   768
#define H_   12
#define L_   4
#define DFF_ 3072
#define NT_  (B_*N_)        // 6272 tokens
#define BNC_ (NT_*C_)       // 4816896

// ---------------- scratch (no cudaMalloc allowed) ----------------
__device__ float g_cur[2][BNC_];          // post-fusion / residual stream x,y
__device__ float g_ln[BNC_];              // layernorm output
__device__ float g_qkv[NT_*3*C_];         // qkv projection
__device__ float g_attn[BNC_];            // attention output (pre-proj)
__device__ float g_S[B_*H_*N_*N_];        // attention scores
__device__ float g_hidden[NT_*DFF_];      // mlp hidden
__device__ float g_fused[B_*L_*C_];       // latent fusion output
__device__ float g_fscore[B_*L_*2*N_];    // latent fusion scores

// ---------------- tf32 helpers ----------------
__device__ __forceinline__ unsigned f2tf(float x){
    unsigned u; asm("cvt.rna.tf32.f32 %0, %1;" : "=r"(u) : "f"(x)); return u;
}

__device__ __forceinline__ void mma8(float* d, const unsigned* a, const unsigned* b){
    asm volatile("mma.sync.aligned.m16n8k8.row.col.f32.tf32.tf32.f32 "
        "{%0,%1,%2,%3}, {%4,%5,%6,%7}, {%8,%9}, {%0,%1,%2,%3};\n"
        : "+f"(d[0]), "+f"(d[1]), "+f"(d[2]), "+f"(d[3])
        : "r"(a[0]), "r"(a[1]), "r"(a[2]), "r"(a[3]), "r"(b[0]), "r"(b[1]));
}

// ---------------- generic batched GEMM: C = alpha*(A@B) [+bias] [gelu] [+Res] ----------------
// A: [M,K] row-major (lda). B: if !transB, [K,N] row-major (ldb); if transB,
// source is [N,K] row-major (ldb) interpreted as B[k][n] = src[n][k].
// Batch z decomposes as zo = z/inner, zi = z%inner; operand offset =
// zo*s1 + zi*s2 (maps the (b,h) strided qkv layout directly).
#define BM  128
#define BN  128
#define BKT 16
#define BKP 20
#define BNP 136

__global__ void __launch_bounds__(256)
gemm_tf32_kernel(const float* __restrict__ A, int lda, long sA1, long sA2,
                 const float* __restrict__ Bg, int ldb, long sB1, long sB2, int transB,
                 float* __restrict__ C, int ldc, long sC1, long sC2,
                 const float* __restrict__ bias,
                 const float* __restrict__ Res, int ldres, long sR1, long sR2,
                 int M, int N, int K, int inner, float alpha, int op)
{
    __shared__ float As[2][BM][BKP];
    __shared__ float Bs[2][BKT][BNP];

    const int z  = blockIdx.z;
    const int zo = z / inner, zi = z - zo*inner;
    const float* Ab = A  + (long)zo*sA1 + (long)zi*sA2;
    const float* Bb = Bg + (long)zo*sB1 + (long)zi*sB2;
    float*       Cb = C  + (long)zo*sC1 + (long)zi*sC2;
    const float* Rb = Res ? (Res + (long)zo*sR1 + (long)zi*sR2) : (const float*)0;

    const int row0 = blockIdx.y * BM;
    const int col0 = blockIdx.x * BN;
    const int tid  = threadIdx.x;
    const int warp = tid >> 5, lane = tid & 31;
    const int wm = warp >> 1, wn = warp & 1;        // 4x2 warp grid -> 32x64 warp tile
    const int g  = lane >> 2, tg = lane & 3;

    float acc[16][4];
    #pragma unroll
    for (int i = 0; i < 16; i++){ acc[i][0]=0.f; acc[i][1]=0.f; acc[i][2]=0.f; acc[i][3]=0.f; }

    const int ktiles = (K + BKT - 1) / BKT;

    // --- per-thread load indices (constant across tiles) ---
    const int a_m   = tid >> 1;
    const int a_kk0 = (tid & 1) * 8;
    const bool a_rok = (row0 + a_m < M);
    const float* a_base = Ab + (long)(row0 + a_m) * lda + a_kk0;

    const int bn_kk = tid >> 4;           // !transB
    const int bn_n0 = (tid & 15) * 8;
    const int bt_nb  = tid >> 2;          // transB
    const int bt_kk0 = (tid & 3) * 4;

    float ar[8], br[8];

    // fetch tile kt's operands into registers (LDGs issued; no smem yet)
    auto fetchRegs = [&](int kt){
        const int k0 = kt * BKT;
        #pragma unroll
        for (int i = 0; i < 8; i++){
            int k = k0 + a_kk0 + i;
            ar[i] = (a_rok && k < K) ? a_base[k0 + i] : 0.f;
        }
        if (!transB){
            int k = k0 + bn_kk;
            const float* bp = Bb + (long)k*ldb + col0 + bn_n0;
            bool kok = (k < K);
            #pragma unroll
            for (int i = 0; i < 8; i++){
                int gn = col0 + bn_n0 + i;
                br[i] = (kok && gn < N) ? bp[i] : 0.f;
            }
        } else {
            #pragma unroll
            for (int p = 0; p < 2; p++){
                int gn = col0 + bt_nb + p * 64;
                const float* bp = Bb + (long)gn*ldb + k0 + bt_kk0;
                bool nok = (gn < N);
                #pragma unroll
                for (int i = 0; i < 4; i++){
                    int k = k0 + bt_kk0 + i;
                    br[p*4 + i] = (nok && k < K) ? bp[i] : 0.f;
                }
            }
        }
    };

    // store registers into smem buffer s
    auto storeRegs = [&](int s){
        #pragma unroll
        for (int i = 0; i < 8; i++) As[s][a_m][a_kk0 + i] = ar[i];
        if (!transB){
            #pragma unroll
            for (int i = 0; i < 8; i++) Bs[s][bn_kk][bn_n0 + i] = br[i];
        } else {
            #pragma unroll
            for (int p = 0; p < 2; p++)
                #pragma unroll
                for (int i = 0; i < 4; i++)
                    Bs[s][bt_kk0 + i][bt_nb + p*64] = br[p*4 + i];
        }
    };

    fetchRegs(0);
    storeRegs(0);
    __syncthreads();

    for (int kt = 0; kt < ktiles; kt++){
        const int s = kt & 1;
        const bool more = (kt + 1 < ktiles);
        if (more) fetchRegs(kt + 1);           // LDGs in flight during MMAs

        #pragma unroll
        for (int ks = 0; ks < 2; ks++){
            const int kb = ks * 8;
            unsigned af[2][4];
            #pragma unroll
            for (int mt = 0; mt < 2; mt++){
                int r = wm*32 + mt*16 + g;
                af[mt][0] = f2tf(As[s][r    ][kb + tg    ]);
                af[mt][1] = f2tf(As[s][r + 8][kb + tg    ]);
                af[mt][2] = f2tf(As[s][r    ][kb + tg + 4]);
                af[mt][3] = f2tf(As[s][r + 8][kb + tg + 4]);
            }
            unsigned bf[8][2];
            #pragma unroll
            for (int nt = 0; nt < 8; nt++){
                int c = wn*64 + nt*8 + g;
                bf[nt][0] = f2tf(Bs[s][kb + tg    ][c]);
                bf[nt][1] = f2tf(Bs[s][kb + tg + 4][c]);
            }
            #pragma unroll
            for (int mt = 0; mt < 2; mt++)
                #pragma unroll
                for (int nt = 0; nt < 8; nt++)
                    mma8(acc[mt*8 + nt], af[mt], bf[nt]);
        }

        if (more){
            storeRegs(s ^ 1);                  // pay load latency only here
        }
        __syncthreads();
    }

    // ---------------- epilogue ----------------
    const bool fullTile = (row0 + BM <= M) && (col0 + BN <= N);
    if (fullTile){
        #pragma unroll
        for (int mt = 0; mt < 2; mt++){
            #pragma unroll
            for (int nt = 0; nt < 8; nt++){
                const float* a = acc[mt*8 + nt];
                int rbase = row0 + wm*32 + mt*16 + g;
                int cbase = col0 + wn*64 + nt*8 + tg*2;
                float b0 = bias ? bias[cbase]     : 0.f;
                float b1 = bias ? bias[cbase + 1] : 0.f;
                #pragma unroll
                for (int h = 0; h < 2; h++){
                    int r = rbase + h*8;
                    float v0 = a[h*2]     * alpha + b0;
                    float v1 = a[h*2 + 1] * alpha + b1;
                    if (op == 1){
                        v0 = 0.5f * v0 * (1.0f + erff(v0 * 0.70710678118654752f));
                        v1 = 0.5f * v1 * (1.0f + erff(v1 * 0.70710678118654752f));
                    }
                    if (Rb){
                        v0 += Rb[(long)r*ldres + cbase];
                        v1 += Rb[(long)r*ldres + cbase + 1];
                    }
                    Cb[(long)r*ldc + cbase]     = v0;
                    Cb[(long)r*ldc + cbase + 1] = v1;
                }
            }
        }
    } else {
        #pragma unroll
        for (int mt = 0; mt < 2; mt++){
            #pragma unroll
            for (int nt = 0; nt < 8; nt++){
                const float* a = acc[mt*8 + nt];
                int rbase = row0 + wm*32 + mt*16 + g;
                int cbase = col0 + wn*64 + nt*8 + tg*2;
                #pragma unroll
                for (int e = 0; e < 4; e++){
                    int r = rbase + (e >> 1) * 8;
                    int c = cbase + (e & 1);
                    if (r < M && c < N){
                        float v = a[e] * alpha;
                        if (bias) v += bias[c];
                        if (op == 1) v = 0.5f * v * (1.0f + erff(v * 0.70710678118654752f));
                        if (Rb) v += Rb[(long)r*ldres + c];
                        Cb[(long)r*ldc + c] = v;
                    }
                }
            }
        }
    }
}

// ---------------- LayerNorm (C=768, 256 threads/row) ----------------
__device__ __forceinline__ float blockReduceSum256(float v){
    __shared__ float sh[8];
    __shared__ float total;
    int lane = threadIdx.x & 31, w = threadIdx.x >> 5;
    #pragma unroll
    for (int o = 16; o; o >>= 1) v += __shfl_xor_sync(0xffffffffu, v, o);
    if (lane == 0) sh[w] = v;
    __syncthreads();
    if (threadIdx.x == 0){
        float t = 0.f;
        #pragma unroll
        for (int i = 0; i < 8; i++) t += sh[i];
        total = t;
    }
    __syncthreads();
    float r = total;
    __syncthreads();
    return r;
}

__global__ void ln_kernel(const float* __restrict__ x, const float* __restrict__ gam,
                          const float* __restrict__ bet, float* __restrict__ out)
{
    const int row = blockIdx.x;
    const float* xr = x + (long)row * C_;
    float* orow = out + (long)row * C_;
    const int tid = threadIdx.x;

    float v0 = xr[tid], v1 = xr[tid + 256], v2 = xr[tid + 512];
    float mean = blockReduceSum256(v0 + v1 + v2) * (1.f / 768.f);
    float d0 = v0 - mean, d1 = v1 - mean, d2 = v2 - mean;
    float var = blockReduceSum256(d0*d0 + d1*d1 + d2*d2) * (1.f / 768.f);
    float rstd = rsqrtf(var + 1e-6f);
    orow[tid      ] = d0 * rstd * gam[tid      ] + bet[tid      ];
    orow[tid + 256] = d1 * rstd * gam[tid + 256] + bet[tid + 256];
    orow[tid + 512] = d2 * rstd * gam[tid + 512] + bet[tid + 512];
}

// ---------------- row softmax (warp per row) ----------------
__global__ void softmax_rows(float* __restrict__ S, int rows, int cols)
{
    int row = blockIdx.x * 8 + (threadIdx.x >> 5);
    if (row >= rows) return;
    int lane = threadIdx.x & 31;
    float* r = S + (long)row * cols;
    float m = -1e30f;
    for (int j = lane; j < cols; j += 32) m = fmaxf(m, r[j]);
    #pragma unroll
    for (int o = 16; o; o >>= 1) m = fmaxf(m, __shfl_xor_sync(0xffffffffu, m, o));
    float s = 0.f;
    for (int j = lane; j < cols; j += 32){ float e = __expf(r[j] - m); r[j] = e; s += e; }
    #pragma unroll
    for (int o = 16; o; o >>= 1) s += __shfl_xor_sync(0xffffffffu, s, o);
    float inv = 1.f / s;
    for (int j = lane; j < cols; j += 32) r[j] *= inv;
}

// ---------------- latent-fusion apply: out = x + scale * sdpa(x, fused, fused) ----------------
__global__ void fuse_apply(const float* __restrict__ x, const float* __restrict__ fused,
                           const float* __restrict__ scale, float* __restrict__ out)
{
    const int row = blockIdx.x;              // b*N + n
    const int b = row / N_;
    const float* xr = x + (long)row * C_;
    const float* fb = fused + (long)b * L_ * C_;
    const int tid = threadIdx.x;

    float acc[L_] = {0.f, 0.f, 0.f, 0.f};
    for (int d = tid; d < C_; d += 256){
        float xv = xr[d];
        #pragma unroll
        for (int l = 0; l < L_; l++) acc[l] += xv * fb[l*C_ + d];
    }
    __shared__ float sred[L_][8];
    __shared__ float sp[L_];
    int lane = tid & 31, w = tid >> 5;
    #pragma unroll
    for (int l = 0; l < L_; l++){
        float v = acc[l];
        #pragma unroll
        for (int o = 16; o; o >>= 1) v += __shfl_xor_sync(0xffffffffu, v, o);
        if (lane == 0) sred[l][w] = v;
    }
    __syncthreads();
    if (tid == 0){
        float s[L_]; float m = -1e30f;
        #pragma unroll
        for (int l = 0; l < L_; l++){
            float t = 0.f;
            #pragma unroll
            for (int ww = 0; ww < 8; ww++) t += sred[l][ww];
            t *= 0.03608439182435161f;       // 768^-0.5
            s[l] = t; m = fmaxf(m, t);
        }
        float sum = 0.f;
        #pragma unroll
        for (int l = 0; l < L_; l++){ s[l] = __expf(s[l] - m); sum += s[l]; }
        float inv = 1.f / sum;
        #pragma unroll
        for (int l = 0; l < L_; l++) sp[l] = s[l] * inv;
    }
    __syncthreads();
    float sc = scale[0];
    float p0 = sp[0], p1 = sp[1], p2 = sp[2], p3 = sp[3];
    for (int d = tid; d < C_; d += 256){
        float v = p0*fb[d] + p1*fb[C_ + d] + p2*fb[2*C_ + d] + p3*fb[3*C_ + d];
        out[(long)row*C_ + d] = xr[d] + sc * v;
    }
}

// ---------------- host side ----------------
static inline void gemm(const float* A, int lda, long sA1, long sA2,
                        const float* Bg, int ldb, long sB1, long sB2, int transB,
                        float* C, int ldc, long sC1, long sC2,
                        const float* bias,
                        const float* Res, int ldres, long sR1, long sR2,
                        int M, int N, int K, int batch, int inner, float alpha, int op)
{
    dim3 grid((N + BN - 1) / BN, (M + BM - 1) / BM, batch);
    gemm_tf32_kernel<<<grid, 256>>>(A, lda, sA1, sA2, Bg, ldb, sB1, sB2, transB,
                                    C, ldc, sC1, sC2, bias, Res, ldres, sR1, sR2,
                                    M, N, K, inner, alpha, op);
}

extern "C" void kernel_launch(void* const* d_in, const int* in_sizes, int n_in,
                              void* d_out, int out_size)
{
    const float* x       = (const float*)d_in[0];
    const float* y       = (const float*)d_in[1];
    const float* lat     = (const float*)d_in[2];
    const float* scale_a = (const float*)d_in[3];
    const float* scale_v = (const float*)d_in[4];

    float *curx, *lnbuf, *qkvbuf, *attnbuf, *Sbuf, *hid, *fused, *fscore;
    cudaGetSymbolAddress((void**)&curx,   g_cur);
    cudaGetSymbolAddress((void**)&lnbuf,  g_ln);
    cudaGetSymbolAddress((void**)&qkvbuf, g_qkv);
    cudaGetSymbolAddress((void**)&attnbuf,g_attn);
    cudaGetSymbolAddress((void**)&Sbuf,   g_S);
    cudaGetSymbolAddress((void**)&hid,    g_hidden);
    cudaGetSymbolAddress((void**)&fused,  g_fused);
    cudaGetSymbolAddress((void**)&fscore, g_fscore);
    float* cury = curx + BNC_;

    const float scC = 0.03608439182435161f;   // C^-0.5

    // ---- latent bottleneck fusion ----
    gemm(lat, C_, 0, 0,  x, C_, (long)N_*C_, 0, 1,
         fscore, 2*N_, (long)L_*2*N_, 0, 0, 0, 0, 0, 0,
         L_, N_, C_, B_, 1, scC, 0);
    gemm(lat, C_, 0, 0,  y, C_, (long)N_*C_, 0, 1,
         fscore + N_, 2*N_, (long)L_*2*N_, 0, 0, 0, 0, 0, 0,
         L_, N_, C_, B_, 1, scC, 0);
    softmax_rows<<<(B_*L_ + 7)/8, 256>>>(fscore, B_*L_, 2*N_);
    gemm(fscore, 2*N_, (long)L_*2*N_, 0,  x, C_, (long)N_*C_, 0, 0,
         fused, C_, (long)L_*C_, 0, 0, 0, 0, 0, 0,
         L_, C_, N_, B_, 1, 1.f, 0);
    gemm(fscore + N_, 2*N_, (long)L_*2*N_, 0,  y, C_, (long)N_*C_, 0, 0,
         fused, C_, (long)L_*C_, 0, 0, fused, C_, (long)L_*C_, 0,
         L_, C_, N_, B_, 1, 1.f, 0);
    fuse_apply<<<NT_, 256>>>(x, fused, scale_a, curx);
    fuse_apply<<<NT_, 256>>>(y, fused, scale_v, cury);

    // ---- per-stream ViT block ----
    for (int st = 0; st < 2; st++){
        const float* ln1g = (const float*)d_in[5 + st*12 + 0];
        const float* ln1b = (const float*)d_in[5 + st*12 + 1];
        const float* qkvw = (const float*)d_in[5 + st*12 + 2];
        const float* qkvb = (const float*)d_in[5 + st*12 + 3];
        const float* projw= (const float*)d_in[5 + st*12 + 4];
        const float* projb= (const float*)d_in[5 + st*12 + 5];
        const float* ln2g = (const float*)d_in[5 + st*12 + 6];
        const float* ln2b = (const float*)d_in[5 + st*12 + 7];
        const float* fc1w = (const float*)d_in[5 + st*12 + 8];
        const float* fc1b = (const float*)d_in[5 + st*12 + 9];
        const float* fc2w = (const float*)d_in[5 + st*12 + 10];
        const float* fc2b = (const float*)d_in[5 + st*12 + 11];

        float* cur  = st ? cury : curx;
        float* outp = (float*)d_out + (long)st * BNC_;

        // attn branch
        ln_kernel<<<NT_, 256>>>(cur, ln1g, ln1b, lnbuf);
        gemm(lnbuf, C_, 0, 0,  qkvw, 3*C_, 0, 0, 0,
             qkvbuf, 3*C_, 0, 0, qkvb, 0, 0, 0, 0,
             NT_, 3*C_, C_, 1, 1, 1.f, 0);
        // S = (Q @ K^T) * hd^-0.5 ; batch z = b*H + h
        gemm(qkvbuf, 3*C_, (long)N_*3*C_, 64,
             qkvbuf + C_, 3*C_, (long)N_*3*C_, 64, 1,
             Sbuf, N_, (long)H_*N_*N_, (long)N_*N_, 0, 0, 0, 0, 0,
             N_, N_, 64, B_*H_, H_, 0.125f, 0);
        softmax_rows<<<(B_*H_*N_ + 7)/8, 256>>>(Sbuf, B_*H_*N_, N_);
        // O = P @ V, written to [B,N,C] with head offset
        gemm(Sbuf, N_, (long)H_*N_*N_, (long)N_*N_,
             qkvbuf + 2*C_, 3*C_, (long)N_*3*C_, 64, 0,
             attnbuf, C_, (long)N_*C_, 64, 0, 0, 0, 0, 0,
             N_, 64, N_, B_*H_, H_, 1.f, 0);
        // x = x + O @ proj_w + proj_b   (in-place residual update)
        gemm(attnbuf, C_, 0, 0,  projw, C_, 0, 0, 0,
             cur, C_, 0, 0, projb, cur, C_, 0, 0,
             NT_, C_, C_, 1, 1, 1.f, 0);

        // mlp branch
        ln_kernel<<<NT_, 256>>>(cur, ln2g, ln2b, lnbuf);
        gemm(lnbuf, C_, 0, 0,  fc1w, DFF_, 0, 0, 0,
             hid, DFF_, 0, 0, fc1b, 0, 0, 0, 0,
             NT_, DFF_, C_, 1, 1, 1.f, 1 /*gelu*/);
        gemm(hid, DFF_, 0, 0,  fc2w, C_, 0, 0, 0,
             outp, C_, 0, 0, fc2b, cur, C_, 0, 0,
             NT_, C_, DFF_, 1, 1, 1.f, 0);
    }
}

// round 9
// speedup vs baseline: 2.1578x; 2.1578x over previous
#include <cuda_runtime.h>
#include <math.h>

#define B_   32
#define N_   196
#define C_   768
#define H_   12
#define L_   4
#define DFF_ 3072
#define NT_  (B_*N_)        // 6272 tokens
#define BNC_ (NT_*C_)       // 4816896

// ---------------- scratch (no cudaMalloc allowed; 16B-aligned for cp.async) ----
__device__ __align__(256) float g_cur[2][BNC_];
__device__ __align__(256) float g_ln[BNC_];
__device__ __align__(256) float g_qkv[NT_*3*C_];
__device__ __align__(256) float g_attn[BNC_];
__device__ __align__(256) float g_S[B_*H_*N_*N_];
__device__ __align__(256) float g_hidden[NT_*DFF_];
__device__ __align__(256) float g_fused[B_*L_*C_];
__device__ __align__(256) float g_fscore[B_*L_*2*N_];

// ---------------- mma helper (tf32 operands passed as raw fp32 bits) ----------
__device__ __forceinline__ void mma8(float* d, const unsigned* a, const unsigned* b){
    asm volatile("mma.sync.aligned.m16n8k8.row.col.f32.tf32.tf32.f32 "
        "{%0,%1,%2,%3}, {%4,%5,%6,%7}, {%8,%9}, {%0,%1,%2,%3};\n"
        : "+f"(d[0]), "+f"(d[1]), "+f"(d[2]), "+f"(d[3])
        : "r"(a[0]), "r"(a[1]), "r"(a[2]), "r"(a[3]), "r"(b[0]), "r"(b[1]));
}

// ---------------- cp.async helpers ----------------
__device__ __forceinline__ void cpa16(unsigned dst, const void* src, int bytes){
    asm volatile("cp.async.cg.shared.global [%0], [%1], 16, %2;\n"
                 :: "r"(dst), "l"(src), "r"(bytes));
}
__device__ __forceinline__ void cpcommit(){ asm volatile("cp.async.commit_group;\n"); }
__device__ __forceinline__ void cpwait1(){ asm volatile("cp.async.wait_group 1;\n"); }
__device__ __forceinline__ int clamp4b(int v){ return (v < 0 ? 0 : (v > 4 ? 4 : v)) * 4; }

// ---------------- generic batched GEMM: C = alpha*(A@B) [+bias] [gelu] [+Res] --
// A: [M,K] row-major (lda). B: if !transB, [K,N] row-major (ldb); if transB,
// source is [N,K] row-major (ldb), B[k][n] = src[n][k].
// Batch z: zo=z/inner, zi=z%inner; operand offset = zo*s1 + zi*s2.
#define BM  128
#define BN  128
#define BKT 16
#define BKP 20
#define BNP 136
#define ASTG_F (BM*BKP)          // 2560 floats per A stage
#define BSTG_F 2560              // max(BKT*BNP=2176, 128*BKP=2560)

__global__ void __launch_bounds__(256, 2)
gemm_tf32_kernel(const float* __restrict__ A, int lda, long sA1, long sA2,
                 const float* __restrict__ Bg, int ldb, long sB1, long sB2, int transB,
                 float* __restrict__ C, int ldc, long sC1, long sC2,
                 const float* __restrict__ bias,
                 const float* __restrict__ Res, int ldres, long sR1, long sR2,
                 int M, int N, int K, int inner, float alpha, int op)
{
    __shared__ __align__(16) float As[2][ASTG_F];
    __shared__ __align__(16) float Bs[2][BSTG_F];

    const int z  = blockIdx.z;
    const int zo = z / inner, zi = z - zo*inner;
    const float* Ab = A  + (long)zo*sA1 + (long)zi*sA2;
    const float* Bb = Bg + (long)zo*sB1 + (long)zi*sB2;
    float*       Cb = C  + (long)zo*sC1 + (long)zi*sC2;
    const float* Rb = Res ? (Res + (long)zo*sR1 + (long)zi*sR2) : (const float*)0;

    const int row0 = blockIdx.y * BM;
    const int col0 = blockIdx.x * BN;
    const int tid  = threadIdx.x;
    const int warp = tid >> 5, lane = tid & 31;
    const int wm = warp >> 1, wn = warp & 1;        // 4x2 warps -> 32x64 warp tile
    const int g  = lane >> 2, tg = lane & 3;

    float acc[16][4];
    #pragma unroll
    for (int i = 0; i < 16; i++){ acc[i][0]=0.f; acc[i][1]=0.f; acc[i][2]=0.f; acc[i][3]=0.f; }

    const int ktiles = (K + BKT - 1) / BKT;

    // ---- per-thread load geometry ----
    const int a_m   = tid >> 1;
    const int a_kk0 = (tid & 1) * 8;
    const bool a_rok = (row0 + a_m) < M;
    const float* a_src = Ab + (long)min(row0 + a_m, M - 1) * lda + a_kk0;
    const unsigned a_dst = (unsigned)__cvta_generic_to_shared(&As[0][a_m*BKP + a_kk0]);

    const int bn_kk = tid >> 4;
    const int bn_n0 = (tid & 15) * 8;
    const int bt_nb  = tid >> 2;
    const int bt_kk0 = (tid & 3) * 4;
    const unsigned b_dst_n = (unsigned)__cvta_generic_to_shared(&Bs[0][bn_kk*BNP + bn_n0]);
    const unsigned b_dst_t = (unsigned)__cvta_generic_to_shared(&Bs[0][bt_nb*BKP + bt_kk0]);
    const unsigned b_dst_t2= (unsigned)__cvta_generic_to_shared(&Bs[0][(bt_nb+64)*BKP + bt_kk0]);

    auto issueTile = [&](int kt, int s){
        const int k0 = kt * BKT;
        {   // A: two 16B chunks
            int kl = K - (k0 + a_kk0);
            int b0 = a_rok ? clamp4b(kl)     : 0;
            int b1 = a_rok ? clamp4b(kl - 4) : 0;
            unsigned d = a_dst + (unsigned)(s * ASTG_F * 4);
            cpa16(d,      a_src + (b0 ? k0 : 0),     b0);
            cpa16(d + 16, a_src + (b1 ? k0 + 4 : 0), b1);
        }
        if (!transB){
            int k = k0 + bn_kk;
            bool kok = (k < K);
            long roff = (long)min(k, K - 1) * ldb;
            int cb = col0 + bn_n0;
            int b0 = kok ? clamp4b(N - cb)     : 0;
            int b1 = kok ? clamp4b(N - cb - 4) : 0;
            unsigned d = b_dst_n + (unsigned)(s * BSTG_F * 4);
            cpa16(d,      Bb + roff + (b0 ? cb     : 0), b0);
            cpa16(d + 16, Bb + roff + (b1 ? cb + 4 : 0), b1);
        } else {
            int kk = k0 + bt_kk0;
            int kb = clamp4b(K - kk);
            int gn0 = col0 + bt_nb;
            int gn1 = gn0 + 64;
            int b0 = (gn0 < N) ? kb : 0;
            int b1 = (gn1 < N) ? kb : 0;
            cpa16(b_dst_t  + (unsigned)(s * BSTG_F * 4),
                  Bb + (long)(b0 ? gn0 : 0)*ldb + (b0 ? kk : 0), b0);
            cpa16(b_dst_t2 + (unsigned)(s * BSTG_F * 4),
                  Bb + (long)(b1 ? gn1 : 0)*ldb + (b1 ? kk : 0), b1);
        }
    };

    issueTile(0, 0); cpcommit();
    if (ktiles > 1) issueTile(1, 1);
    cpcommit();

    for (int kt = 0; kt < ktiles; kt++){
        const int s = kt & 1;
        cpwait1();
        __syncthreads();

        const float* Asp = As[s];
        const float* Bsp = Bs[s];
        #pragma unroll
        for (int ks = 0; ks < 2; ks++){
            const int kb = ks * 8;
            unsigned af[2][4];
            #pragma unroll
            for (int mt = 0; mt < 2; mt++){
                int r = wm*32 + mt*16 + g;
                af[mt][0] = __float_as_uint(Asp[ r     *BKP + kb + tg    ]);
                af[mt][1] = __float_as_uint(Asp[(r + 8)*BKP + kb + tg    ]);
                af[mt][2] = __float_as_uint(Asp[ r     *BKP + kb + tg + 4]);
                af[mt][3] = __float_as_uint(Asp[(r + 8)*BKP + kb + tg + 4]);
            }
            unsigned bf[8][2];
            if (!transB){
                #pragma unroll
                for (int nt = 0; nt < 8; nt++){
                    int c = wn*64 + nt*8 + g;
                    bf[nt][0] = __float_as_uint(Bsp[(kb + tg    )*BNP + c]);
                    bf[nt][1] = __float_as_uint(Bsp[(kb + tg + 4)*BNP + c]);
                }
            } else {
                #pragma unroll
                for (int nt = 0; nt < 8; nt++){
                    int c = wn*64 + nt*8 + g;
                    bf[nt][0] = __float_as_uint(Bsp[c*BKP + kb + tg    ]);
                    bf[nt][1] = __float_as_uint(Bsp[c*BKP + kb + tg + 4]);
                }
            }
            #pragma unroll
            for (int mt = 0; mt < 2; mt++)
                #pragma unroll
                for (int nt = 0; nt < 8; nt++)
                    mma8(acc[mt*8 + nt], af[mt], bf[nt]);
        }

        __syncthreads();
        if (kt + 2 < ktiles) issueTile(kt + 2, s);
        cpcommit();
    }

    // ---------------- epilogue ----------------
    const bool fullTile = (row0 + BM <= M) && (col0 + BN <= N);
    if (fullTile){
        #pragma unroll
        for (int mt = 0; mt < 2; mt++){
            #pragma unroll
            for (int nt = 0; nt < 8; nt++){
                const float* a = acc[mt*8 + nt];
                int rbase = row0 + wm*32 + mt*16 + g;
                int cbase = col0 + wn*64 + nt*8 + tg*2;
                float b0 = bias ? bias[cbase]     : 0.f;
                float b1 = bias ? bias[cbase + 1] : 0.f;
                #pragma unroll
                for (int h = 0; h < 2; h++){
                    int r = rbase + h*8;
                    float v0 = a[h*2]     * alpha + b0;
                    float v1 = a[h*2 + 1] * alpha + b1;
                    if (op == 1){
                        v0 = 0.5f * v0 * (1.0f + erff(v0 * 0.70710678118654752f));
                        v1 = 0.5f * v1 * (1.0f + erff(v1 * 0.70710678118654752f));
                    }
                    if (Rb){
                        v0 += Rb[(long)r*ldres + cbase];
                        v1 += Rb[(long)r*ldres + cbase + 1];
                    }
                    Cb[(long)r*ldc + cbase]     = v0;
                    Cb[(long)r*ldc + cbase + 1] = v1;
                }
            }
        }
    } else {
        #pragma unroll
        for (int mt = 0; mt < 2; mt++){
            #pragma unroll
            for (int nt = 0; nt < 8; nt++){
                const float* a = acc[mt*8 + nt];
                int rbase = row0 + wm*32 + mt*16 + g;
                int cbase = col0 + wn*64 + nt*8 + tg*2;
                #pragma unroll
                for (int e = 0; e < 4; e++){
                    int r = rbase + (e >> 1) * 8;
                    int c = cbase + (e & 1);
                    if (r < M && c < N){
                        float v = a[e] * alpha;
                        if (bias) v += bias[c];
                        if (op == 1) v = 0.5f * v * (1.0f + erff(v * 0.70710678118654752f));
                        if (Rb) v += Rb[(long)r*ldres + c];
                        Cb[(long)r*ldc + c] = v;
                    }
                }
            }
        }
    }
}

// ---------------- LayerNorm (C=768, 256 threads/row) ----------------
__device__ __forceinline__ float blockReduceSum256(float v){
    __shared__ float sh[8];
    __shared__ float total;
    int lane = threadIdx.x & 31, w = threadIdx.x >> 5;
    #pragma unroll
    for (int o = 16; o; o >>= 1) v += __shfl_xor_sync(0xffffffffu, v, o);
    if (lane == 0) sh[w] = v;
    __syncthreads();
    if (threadIdx.x == 0){
        float t = 0.f;
        #pragma unroll
        for (int i = 0; i < 8; i++) t += sh[i];
        total = t;
    }
    __syncthreads();
    float r = total;
    __syncthreads();
    return r;
}

__global__ void ln_kernel(const float* __restrict__ x, const float* __restrict__ gam,
                          const float* __restrict__ bet, float* __restrict__ out)
{
    const int row = blockIdx.x;
    const float* xr = x + (long)row * C_;
    float* orow = out + (long)row * C_;
    const int tid = threadIdx.x;

    float v0 = xr[tid], v1 = xr[tid + 256], v2 = xr[tid + 512];
    float mean = blockReduceSum256(v0 + v1 + v2) * (1.f / 768.f);
    float d0 = v0 - mean, d1 = v1 - mean, d2 = v2 - mean;
    float var = blockReduceSum256(d0*d0 + d1*d1 + d2*d2) * (1.f / 768.f);
    float rstd = rsqrtf(var + 1e-6f);
    orow[tid      ] = d0 * rstd * gam[tid      ] + bet[tid      ];
    orow[tid + 256] = d1 * rstd * gam[tid + 256] + bet[tid + 256];
    orow[tid + 512] = d2 * rstd * gam[tid + 512] + bet[tid + 512];
}

// ---------------- row softmax (warp per row) ----------------
__global__ void softmax_rows(float* __restrict__ S, int rows, int cols)
{
    int row = blockIdx.x * 8 + (threadIdx.x >> 5);
    if (row >= rows) return;
    int lane = threadIdx.x & 31;
    float* r = S + (long)row * cols;
    float m = -1e30f;
    for (int j = lane; j < cols; j += 32) m = fmaxf(m, r[j]);
    #pragma unroll
    for (int o = 16; o; o >>= 1) m = fmaxf(m, __shfl_xor_sync(0xffffffffu, m, o));
    float s = 0.f;
    for (int j = lane; j < cols; j += 32){ float e = __expf(r[j] - m); r[j] = e; s += e; }
    #pragma unroll
    for (int o = 16; o; o >>= 1) s += __shfl_xor_sync(0xffffffffu, s, o);
    float inv = 1.f / s;
    for (int j = lane; j < cols; j += 32) r[j] *= inv;
}

// ------- latent fusion: P[b,l,:] = softmax( scC * lat[l] . concat[b,j] ) ------
__global__ void lat_score_softmax(const float* __restrict__ x, const float* __restrict__ y,
                                  const float* __restrict__ lat, float* __restrict__ P)
{
    const int b = blockIdx.x;
    const int tid = threadIdx.x;
    __shared__ float slat[L_][C_];
    __shared__ float sS[L_][2*N_];
    for (int i = tid; i < L_*C_; i += 256) ((float*)slat)[i] = lat[i];
    __syncthreads();

    for (int j = tid; j < 2*N_; j += 256){
        const float* row = (j < N_) ? x + ((long)b*N_ + j)*C_
                                    : y + ((long)b*N_ + (j - N_))*C_;
        float a0=0.f, a1=0.f, a2=0.f, a3=0.f;
        for (int d = 0; d < C_; d += 4){
            float4 r = *reinterpret_cast<const float4*>(row + d);
            a0 += r.x*slat[0][d] + r.y*slat[0][d+1] + r.z*slat[0][d+2] + r.w*slat[0][d+3];
            a1 += r.x*slat[1][d] + r.y*slat[1][d+1] + r.z*slat[1][d+2] + r.w*slat[1][d+3];
            a2 += r.x*slat[2][d] + r.y*slat[2][d+1] + r.z*slat[2][d+2] + r.w*slat[2][d+3];
            a3 += r.x*slat[3][d] + r.y*slat[3][d+1] + r.z*slat[3][d+2] + r.w*slat[3][d+3];
        }
        const float scC = 0.03608439182435161f;
        sS[0][j] = a0*scC; sS[1][j] = a1*scC; sS[2][j] = a2*scC; sS[3][j] = a3*scC;
    }
    __syncthreads();

    int w = tid >> 5, lane = tid & 31;
    if (w < L_){
        float m = -1e30f;
        for (int j = lane; j < 2*N_; j += 32) m = fmaxf(m, sS[w][j]);
        #pragma unroll
        for (int o = 16; o; o >>= 1) m = fmaxf(m, __shfl_xor_sync(0xffffffffu, m, o));
        float s = 0.f;
        for (int j = lane; j < 2*N_; j += 32){ float e = __expf(sS[w][j] - m); sS[w][j] = e; s += e; }
        #pragma unroll
        for (int o = 16; o; o >>= 1) s += __shfl_xor_sync(0xffffffffu, s, o);
        float inv = 1.f / s;
        for (int j = lane; j < 2*N_; j += 32)
            P[((long)b*L_ + w)*2*N_ + j] = sS[w][j] * inv;
    }
}

// ------- latent fusion: fused[b,l,d] = sum_j P[b,l,j] * concat[b,j,d] --------
__global__ void lat_out(const float* __restrict__ x, const float* __restrict__ y,
                        const float* __restrict__ P, float* __restrict__ fused)
{
    const int b = blockIdx.x;
    const int tid = threadIdx.x;
    __shared__ float sP[L_][2*N_];
    for (int i = tid; i < L_*2*N_; i += 256) ((float*)sP)[i] = P[(long)b*L_*2*N_ + i];
    __syncthreads();

    float acc[L_][3];
    #pragma unroll
    for (int l = 0; l < L_; l++){ acc[l][0]=0.f; acc[l][1]=0.f; acc[l][2]=0.f; }

    for (int j = 0; j < 2*N_; j++){
        const float* row = (j < N_) ? x + ((long)b*N_ + j)*C_
                                    : y + ((long)b*N_ + (j - N_))*C_;
        float r0 = row[tid], r1 = row[tid + 256], r2 = row[tid + 512];
        #pragma unroll
        for (int l = 0; l < L_; l++){
            float p = sP[l][j];
            acc[l][0] += p*r0; acc[l][1] += p*r1; acc[l][2] += p*r2;
        }
    }
    #pragma unroll
    for (int l = 0; l < L_; l++){
        float* o = fused + ((long)b*L_ + l)*C_;
        o[tid] = acc[l][0]; o[tid + 256] = acc[l][1]; o[tid + 512] = acc[l][2];
    }
}

// ------- fuse apply (both streams): out = in + scale * sdpa(in, fused, fused) -
__global__ void fuse_apply2(const float* __restrict__ x, const float* __restrict__ y,
                            const float* __restrict__ fused,
                            const float* __restrict__ scale_a, const float* __restrict__ scale_v,
                            float* __restrict__ outx, float* __restrict__ outy)
{
    const int row = blockIdx.x;              // b*N + n
    const int st  = blockIdx.y;
    const float* in   = st ? y : x;
    const float* scal = st ? scale_v : scale_a;
    float* out = st ? outy : outx;

    const int b = row / N_;
    const float* xr = in + (long)row * C_;
    const float* fb = fused + (long)b * L_ * C_;
    const int tid = threadIdx.x;

    float acc[L_] = {0.f, 0.f, 0.f, 0.f};
    for (int d = tid; d < C_; d += 256){
        float xv = xr[d];
        #pragma unroll
        for (int l = 0; l < L_; l++) acc[l] += xv * fb[l*C_ + d];
    }
    __shared__ float sred[L_][8];
    __shared__ float sp[L_];
    int lane = tid & 31, w = tid >> 5;
    #pragma unroll
    for (int l = 0; l < L_; l++){
        float v = acc[l];
        #pragma unroll
        for (int o = 16; o; o >>= 1) v += __shfl_xor_sync(0xffffffffu, v, o);
        if (lane == 0) sred[l][w] = v;
    }
    __syncthreads();
    if (tid == 0){
        float s[L_]; float m = -1e30f;
        #pragma unroll
        for (int l = 0; l < L_; l++){
            float t = 0.f;
            #pragma unroll
            for (int ww = 0; ww < 8; ww++) t += sred[l][ww];
            t *= 0.03608439182435161f;
            s[l] = t; m = fmaxf(m, t);
        }
        float sum = 0.f;
        #pragma unroll
        for (int l = 0; l < L_; l++){ s[l] = __expf(s[l] - m); sum += s[l]; }
        float inv = 1.f / sum;
        #pragma unroll
        for (int l = 0; l < L_; l++) sp[l] = s[l] * inv;
    }
    __syncthreads();
    float sc = scal[0];
    float p0 = sp[0], p1 = sp[1], p2 = sp[2], p3 = sp[3];
    for (int d = tid; d < C_; d += 256){
        float v = p0*fb[d] + p1*fb[C_ + d] + p2*fb[2*C_ + d] + p3*fb[3*C_ + d];
        out[(long)row*C_ + d] = xr[d] + sc * v;
    }
}

// ---------------- host side ----------------
static inline void gemm(const float* A, int lda, long sA1, long sA2,
                        const float* Bg, int ldb, long sB1, long sB2, int transB,
                        float* C, int ldc, long sC1, long sC2,
                        const float* bias,
                        const float* Res, int ldres, long sR1, long sR2,
                        int M, int N, int K, int batch, int inner, float alpha, int op)
{
    dim3 grid((N + BN - 1) / BN, (M + BM - 1) / BM, batch);
    gemm_tf32_kernel<<<grid, 256>>>(A, lda, sA1, sA2, Bg, ldb, sB1, sB2, transB,
                                    C, ldc, sC1, sC2, bias, Res, ldres, sR1, sR2,
                                    M, N, K, inner, alpha, op);
}

extern "C" void kernel_launch(void* const* d_in, const int* in_sizes, int n_in,
                              void* d_out, int out_size)
{
    const float* x       = (const float*)d_in[0];
    const float* y       = (const float*)d_in[1];
    const float* lat     = (const float*)d_in[2];
    const float* scale_a = (const float*)d_in[3];
    const float* scale_v = (const float*)d_in[4];

    float *curx, *lnbuf, *qkvbuf, *attnbuf, *Sbuf, *hid, *fused, *fscore;
    cudaGetSymbolAddress((void**)&curx,   g_cur);
    cudaGetSymbolAddress((void**)&lnbuf,  g_ln);
    cudaGetSymbolAddress((void**)&qkvbuf, g_qkv);
    cudaGetSymbolAddress((void**)&attnbuf,g_attn);
    cudaGetSymbolAddress((void**)&Sbuf,   g_S);
    cudaGetSymbolAddress((void**)&hid,    g_hidden);
    cudaGetSymbolAddress((void**)&fused,  g_fused);
    cudaGetSymbolAddress((void**)&fscore, g_fscore);
    float* cury = curx + BNC_;

    // ---- latent bottleneck fusion (custom small kernels) ----
    lat_score_softmax<<<B_, 256>>>(x, y, lat, fscore);
    lat_out<<<B_, 256>>>(x, y, fscore, fused);
    fuse_apply2<<<dim3(NT_, 2), 256>>>(x, y, fused, scale_a, scale_v, curx, cury);

    // ---- per-stream ViT block ----
    for (int st = 0; st < 2; st++){
        const float* ln1g = (const float*)d_in[5 + st*12 + 0];
        const float* ln1b = (const float*)d_in[5 + st*12 + 1];
        const float* qkvw = (const float*)d_in[5 + st*12 + 2];
        const float* qkvb = (const float*)d_in[5 + st*12 + 3];
        const float* projw= (const float*)d_in[5 + st*12 + 4];
        const float* projb= (const float*)d_in[5 + st*12 + 5];
        const float* ln2g = (const float*)d_in[5 + st*12 + 6];
        const float* ln2b = (const float*)d_in[5 + st*12 + 7];
        const float* fc1w = (const float*)d_in[5 + st*12 + 8];
        const float* fc1b = (const float*)d_in[5 + st*12 + 9];
        const float* fc2w = (const float*)d_in[5 + st*12 + 10];
        const float* fc2b = (const float*)d_in[5 + st*12 + 11];

        float* cur  = st ? cury : curx;
        float* outp = (float*)d_out + (long)st * BNC_;

        // attn branch
        ln_kernel<<<NT_, 256>>>(cur, ln1g, ln1b, lnbuf);
        gemm(lnbuf, C_, 0, 0,  qkvw, 3*C_, 0, 0, 0,
             qkvbuf, 3*C_, 0, 0, qkvb, 0, 0, 0, 0,
             NT_, 3*C_, C_, 1, 1, 1.f, 0);
        // S = (Q @ K^T) * hd^-0.5 ; batch z = b*H + h
        gemm(qkvbuf, 3*C_, (long)N_*3*C_, 64,
             qkvbuf + C_, 3*C_, (long)N_*3*C_, 64, 1,
             Sbuf, N_, (long)H_*N_*N_, (long)N_*N_, 0, 0, 0, 0, 0,
             N_, N_, 64, B_*H_, H_, 0.125f, 0);
        softmax_rows<<<(B_*H_*N_ + 7)/8, 256>>>(Sbuf, B_*H_*N_, N_);
        // O = P @ V, written to [B,N,C] with head offset
        gemm(Sbuf, N_, (long)H_*N_*N_, (long)N_*N_,
             qkvbuf + 2*C_, 3*C_, (long)N_*3*C_, 64, 0,
             attnbuf, C_, (long)N_*C_, 64, 0, 0, 0, 0, 0,
             N_, 64, N_, B_*H_, H_, 1.f, 0);
        // x = x + O @ proj_w + proj_b
        gemm(attnbuf, C_, 0, 0,  projw, C_, 0, 0, 0,
             cur, C_, 0, 0, projb, cur, C_, 0, 0,
             NT_, C_, C_, 1, 1, 1.f, 0);

        // mlp branch
        ln_kernel<<<NT_, 256>>>(cur, ln2g, ln2b, lnbuf);
        gemm(lnbuf, C_, 0, 0,  fc1w, DFF_, 0, 0, 0,
             hid, DFF_, 0, 0, fc1b, 0, 0, 0, 0,
             NT_, DFF_, C_, 1, 1, 1.f, 1 /*gelu*/);
        gemm(hid, DFF_, 0, 0,  fc2w, C_, 0, 0, 0,
             outp, C_, 0, 0, fc2b, cur, C_, 0, 0,
             NT_, C_, DFF_, 1, 1, 1.f, 0);
    }
}

// round 11
// speedup vs baseline: 2.3437x; 1.0862x over previous
#include <cuda_runtime.h>
#include <math.h>

#define B_   32
#define N_   196
#define C_   768
#define H_   12
#define L_   4
#define DFF_ 3072
#define NT_  (B_*N_)        // 6272 tokens
#define BNC_ (NT_*C_)       // 4816896

// ---------------- scratch (stream-major contiguous for z-merged batching) ----
__device__ __align__(256) float g_cur[2*BNC_];
__device__ __align__(256) float g_ln[2*BNC_];
__device__ __align__(256) float g_qkv[2*NT_*3*C_];
__device__ __align__(256) float g_attn[2*BNC_];
__device__ __align__(256) float g_S[2*B_*H_*N_*N_];
__device__ __align__(256) float g_hidden[2*(long)NT_*DFF_];
__device__ __align__(256) float g_fused[B_*L_*C_];
__device__ __align__(256) float g_fscore[B_*L_*2*N_];

// ---------------- mma helper (tf32 operands passed as raw fp32 bits) ----------
__device__ __forceinline__ void mma8(float* d, const unsigned* a, const unsigned* b){
    asm volatile("mma.sync.aligned.m16n8k8.row.col.f32.tf32.tf32.f32 "
        "{%0,%1,%2,%3}, {%4,%5,%6,%7}, {%8,%9}, {%0,%1,%2,%3};\n"
        : "+f"(d[0]), "+f"(d[1]), "+f"(d[2]), "+f"(d[3])
        : "r"(a[0]), "r"(a[1]), "r"(a[2]), "r"(a[3]), "r"(b[0]), "r"(b[1]));
}

// ---------------- cp.async helpers ----------------
__device__ __forceinline__ void cpa16(unsigned dst, const void* src, int bytes){
    asm volatile("cp.async.cg.shared.global [%0], [%1], 16, %2;\n"
                 :: "r"(dst), "l"(src), "r"(bytes));
}
__device__ __forceinline__ void cpcommit(){ asm volatile("cp.async.commit_group;\n"); }
__device__ __forceinline__ void cpwait1(){ asm volatile("cp.async.wait_group 1;\n"); }
__device__ __forceinline__ int clamp4b(int v){ return (v < 0 ? 0 : (v > 4 ? 4 : v)) * 4; }

// ---------------- generic batched GEMM, templated on BN ----------------------
// C = alpha*(A@B) [+bias(+stride)] [gelu] [+Res]. Batch z: zo=z/inner, zi=z%inner.
#define BM  128
#define BKT 16
#define BKP 20
#define ASTG_F (BM*BKP)          // 2560 floats per A stage

template<int BNT, int BNPT>
__global__ void __launch_bounds__(256, 2)
gemm_tf32_kernel(const float* __restrict__ A, int lda, long sA1, long sA2,
                 const float* __restrict__ Bg, int ldb, long sB1, long sB2, int transB,
                 float* __restrict__ C, int ldc, long sC1, long sC2,
                 const float* __restrict__ bias, long sBias,
                 const float* __restrict__ Res, int ldres, long sR1, long sR2,
                 int M, int N, int K, int inner, float alpha, int op)
{
    constexpr int NTC  = BNT / 16;                       // n-tiles per warp
    constexpr int BSTG = (BNT == 128) ? 2560 : (BKT * BNPT);

    __shared__ __align__(16) float As[2][ASTG_F];
    __shared__ __align__(16) float Bs[2][BSTG];

    const int z  = blockIdx.z;
    const int zo = z / inner, zi = z - zo*inner;
    const float* Ab = A  + (long)zo*sA1 + (long)zi*sA2;
    const float* Bb = Bg + (long)zo*sB1 + (long)zi*sB2;
    float*       Cb = C  + (long)zo*sC1 + (long)zi*sC2;
    const float* Rb = Res ? (Res + (long)zo*sR1 + (long)zi*sR2) : (const float*)0;
    const float* biasb = bias ? (bias + (long)zo*sBias) : (const float*)0;

    const int row0 = blockIdx.y * BM;
    const int col0 = blockIdx.x * BNT;
    const int tid  = threadIdx.x;
    const int warp = tid >> 5, lane = tid & 31;
    const int wm = warp >> 1, wn = warp & 1;             // 4x2 warps
    const int g  = lane >> 2, tg = lane & 3;

    float acc[2*NTC][4];
    #pragma unroll
    for (int i = 0; i < 2*NTC; i++){ acc[i][0]=0.f; acc[i][1]=0.f; acc[i][2]=0.f; acc[i][3]=0.f; }

    const int ktiles = (K + BKT - 1) / BKT;

    // ---- per-thread load geometry ----
    const int a_m   = tid >> 1;
    const int a_kk0 = (tid & 1) * 8;
    const bool a_rok = (row0 + a_m) < M;
    const float* a_src = Ab + (long)min(row0 + a_m, M - 1) * lda + a_kk0;
    const unsigned a_dst = (unsigned)__cvta_generic_to_shared(&As[0][a_m*BKP + a_kk0]);

    // !transB geometry (BNT=128: 16 rows x 8-float pairs; BNT=64: 16 rows x 4-float)
    const int bn_kk = tid >> 4;
    const int bn_n0 = (BNT == 128) ? (tid & 15) * 8 : (tid & 15) * 4;
    // transB geometry (only BNT=128)
    const int bt_nb  = tid >> 2;
    const int bt_kk0 = (tid & 3) * 4;
    const unsigned b_dst_n = (unsigned)__cvta_generic_to_shared(&Bs[0][bn_kk*BNPT + bn_n0]);
    const unsigned b_dst_t = (unsigned)__cvta_generic_to_shared(&Bs[0][(bt_nb % 64)*BKP + bt_kk0]);
    const unsigned b_dst_t2= (unsigned)__cvta_generic_to_shared(&Bs[0][((bt_nb % 64)+64)*BKP + bt_kk0]);

    auto issueTile = [&](int kt, int s){
        const int k0 = kt * BKT;
        {   // A: two 16B chunks
            int kl = K - (k0 + a_kk0);
            int b0 = a_rok ? clamp4b(kl)     : 0;
            int b1 = a_rok ? clamp4b(kl - 4) : 0;
            unsigned d = a_dst + (unsigned)(s * ASTG_F * 4);
            cpa16(d,      a_src + (b0 ? k0 : 0),     b0);
            cpa16(d + 16, a_src + (b1 ? k0 + 4 : 0), b1);
        }
        if ((BNT == 128) && transB){
            int kk = k0 + bt_kk0;
            int kb = clamp4b(K - kk);
            int gn0 = col0 + bt_nb;
            int gn1 = gn0 + 64;
            int b0 = (gn0 < N) ? kb : 0;
            int b1 = (gn1 < N) ? kb : 0;
            cpa16(b_dst_t  + (unsigned)(s * BSTG * 4),
                  Bb + (long)(b0 ? gn0 : 0)*ldb + (b0 ? kk : 0), b0);
            cpa16(b_dst_t2 + (unsigned)(s * BSTG * 4),
                  Bb + (long)(b1 ? gn1 : 0)*ldb + (b1 ? kk : 0), b1);
        } else {
            int k = k0 + bn_kk;
            bool kok = (k < K);
            long roff = (long)min(k, K - 1) * ldb;
            int cb = col0 + bn_n0;
            unsigned d = b_dst_n + (unsigned)(s * BSTG * 4);
            if (BNT == 128){
                int b0 = kok ? clamp4b(N - cb)     : 0;
                int b1 = kok ? clamp4b(N - cb - 4) : 0;
                cpa16(d,      Bb + roff + (b0 ? cb     : 0), b0);
                cpa16(d + 16, Bb + roff + (b1 ? cb + 4 : 0), b1);
            } else {
                int b0 = kok ? clamp4b(N - cb) : 0;
                cpa16(d, Bb + roff + (b0 ? cb : 0), b0);
            }
        }
    };

    issueTile(0, 0); cpcommit();
    if (ktiles > 1) issueTile(1, 1);
    cpcommit();

    for (int kt = 0; kt < ktiles; kt++){
        const int s = kt & 1;
        cpwait1();
        __syncthreads();

        const float* Asp = As[s];
        const float* Bsp = Bs[s];
        #pragma unroll
        for (int ks = 0; ks < 2; ks++){
            const int kb = ks * 8;
            unsigned af[2][4];
            #pragma unroll
            for (int mt = 0; mt < 2; mt++){
                int r = wm*32 + mt*16 + g;
                af[mt][0] = __float_as_uint(Asp[ r     *BKP + kb + tg    ]);
                af[mt][1] = __float_as_uint(Asp[(r + 8)*BKP + kb + tg    ]);
                af[mt][2] = __float_as_uint(Asp[ r     *BKP + kb + tg + 4]);
                af[mt][3] = __float_as_uint(Asp[(r + 8)*BKP + kb + tg + 4]);
            }
            unsigned bf[NTC][2];
            if ((BNT == 128) && transB){
                #pragma unroll
                for (int nt = 0; nt < NTC; nt++){
                    int c = wn*(BNT/2) + nt*8 + g;
                    bf[nt][0] = __float_as_uint(Bsp[c*BKP + kb + tg    ]);
                    bf[nt][1] = __float_as_uint(Bsp[c*BKP + kb + tg + 4]);
                }
            } else {
                #pragma unroll
                for (int nt = 0; nt < NTC; nt++){
                    int c = wn*(BNT/2) + nt*8 + g;
                    bf[nt][0] = __float_as_uint(Bsp[(kb + tg    )*BNPT + c]);
                    bf[nt][1] = __float_as_uint(Bsp[(kb + tg + 4)*BNPT + c]);
                }
            }
            #pragma unroll
            for (int mt = 0; mt < 2; mt++)
                #pragma unroll
                for (int nt = 0; nt < NTC; nt++)
                    mma8(acc[mt*NTC + nt], af[mt], bf[nt]);
        }

        __syncthreads();
        if (kt + 2 < ktiles) issueTile(kt + 2, s);
        cpcommit();
    }

    // ---------------- epilogue ----------------
    const bool fullTile = (row0 + BM <= M) && (col0 + BNT <= N);
    if (fullTile){
        #pragma unroll
        for (int mt = 0; mt < 2; mt++){
            #pragma unroll
            for (int nt = 0; nt < NTC; nt++){
                const float* a = acc[mt*NTC + nt];
                int rbase = row0 + wm*32 + mt*16 + g;
                int cbase = col0 + wn*(BNT/2) + nt*8 + tg*2;
                float b0 = biasb ? biasb[cbase]     : 0.f;
                float b1 = biasb ? biasb[cbase + 1] : 0.f;
                #pragma unroll
                for (int h = 0; h < 2; h++){
                    int r = rbase + h*8;
                    float v0 = a[h*2]     * alpha + b0;
                    float v1 = a[h*2 + 1] * alpha + b1;
                    if (op == 1){
                        v0 = 0.5f * v0 * (1.0f + erff(v0 * 0.70710678118654752f));
                        v1 = 0.5f * v1 * (1.0f + erff(v1 * 0.70710678118654752f));
                    }
                    if (Rb){
                        v0 += Rb[(long)r*ldres + cbase];
                        v1 += Rb[(long)r*ldres + cbase + 1];
                    }
                    Cb[(long)r*ldc + cbase]     = v0;
                    Cb[(long)r*ldc + cbase + 1] = v1;
                }
            }
        }
    } else {
        #pragma unroll
        for (int mt = 0; mt < 2; mt++){
            #pragma unroll
            for (int nt = 0; nt < NTC; nt++){
                const float* a = acc[mt*NTC + nt];
                int rbase = row0 + wm*32 + mt*16 + g;
                int cbase = col0 + wn*(BNT/2) + nt*8 + tg*2;
                #pragma unroll
                for (int e = 0; e < 4; e++){
                    int r = rbase + (e >> 1) * 8;
                    int c = cbase + (e & 1);
                    if (r < M && c < N){
                        float v = a[e] * alpha;
                        if (biasb) v += biasb[c];
                        if (op == 1) v = 0.5f * v * (1.0f + erff(v * 0.70710678118654752f));
                        if (Rb) v += Rb[(long)r*ldres + c];
                        Cb[(long)r*ldc + c] = v;
                    }
                }
            }
        }
    }
}

// ---------------- LayerNorm (C=768, 256 threads/row) ----------------
__device__ __forceinline__ float blockReduceSum256(float v){
    __shared__ float sh[8];
    __shared__ float total;
    int lane = threadIdx.x & 31, w = threadIdx.x >> 5;
    #pragma unroll
    for (int o = 16; o; o >>= 1) v += __shfl_xor_sync(0xffffffffu, v, o);
    if (lane == 0) sh[w] = v;
    __syncthreads();
    if (threadIdx.x == 0){
        float t = 0.f;
        #pragma unroll
        for (int i = 0; i < 8; i++) t += sh[i];
        total = t;
    }
    __syncthreads();
    float r = total;
    __syncthreads();
    return r;
}

__global__ void ln_kernel(const float* __restrict__ x, const float* __restrict__ gam,
                          const float* __restrict__ bet, float* __restrict__ out)
{
    const int row = blockIdx.x;
    const float* xr = x + (long)row * C_;
    float* orow = out + (long)row * C_;
    const int tid = threadIdx.x;

    float v0 = xr[tid], v1 = xr[tid + 256], v2 = xr[tid + 512];
    float mean = blockReduceSum256(v0 + v1 + v2) * (1.f / 768.f);
    float d0 = v0 - mean, d1 = v1 - mean, d2 = v2 - mean;
    float var = blockReduceSum256(d0*d0 + d1*d1 + d2*d2) * (1.f / 768.f);
    float rstd = rsqrtf(var + 1e-6f);
    orow[tid      ] = d0 * rstd * gam[tid      ] + bet[tid      ];
    orow[tid + 256] = d1 * rstd * gam[tid + 256] + bet[tid + 256];
    orow[tid + 512] = d2 * rstd * gam[tid + 512] + bet[tid + 512];
}

// ---------------- row softmax (warp per row) ----------------
__global__ void softmax_rows(float* __restrict__ S, int rows, int cols)
{
    int row = blockIdx.x * 8 + (threadIdx.x >> 5);
    if (row >= rows) return;
    int lane = threadIdx.x & 31;
    float* r = S + (long)row * cols;
    float m = -1e30f;
    for (int j = lane; j < cols; j += 32) m = fmaxf(m, r[j]);
    #pragma unroll
    for (int o = 16; o; o >>= 1) m = fmaxf(m, __shfl_xor_sync(0xffffffffu, m, o));
    float s = 0.f;
    for (int j = lane; j < cols; j += 32){ float e = __expf(r[j] - m); r[j] = e; s += e; }
    #pragma unroll
    for (int o = 16; o; o >>= 1) s += __shfl_xor_sync(0xffffffffu, s, o);
    float inv = 1.f / s;
    for (int j = lane; j < cols; j += 32) r[j] *= inv;
}

// ------- latent fusion: P[b,l,:] = softmax( scC * lat[l] . concat[b,j] ) ------
__global__ void lat_score_softmax(const float* __restrict__ x, const float* __restrict__ y,
                                  const float* __restrict__ lat, float* __restrict__ P)
{
    const int b = blockIdx.x;
    const int tid = threadIdx.x;
    __shared__ float slat[L_][C_];
    __shared__ float sS[L_][2*N_];
    for (int i = tid; i < L_*C_; i += 256) ((float*)slat)[i] = lat[i];
    __syncthreads();

    for (int j = tid; j < 2*N_; j += 256){
        const float* row = (j < N_) ? x + ((long)b*N_ + j)*C_
                                    : y + ((long)b*N_ + (j - N_))*C_;
        float a0=0.f, a1=0.f, a2=0.f, a3=0.f;
        for (int d = 0; d < C_; d += 4){
            float4 r = *reinterpret_cast<const float4*>(row + d);
            a0 += r.x*slat[0][d] + r.y*slat[0][d+1] + r.z*slat[0][d+2] + r.w*slat[0][d+3];
            a1 += r.x*slat[1][d] + r.y*slat[1][d+1] + r.z*slat[1][d+2] + r.w*slat[1][d+3];
            a2 += r.x*slat[2][d] + r.y*slat[2][d+1] + r.z*slat[2][d+2] + r.w*slat[2][d+3];
            a3 += r.x*slat[3][d] + r.y*slat[3][d+1] + r.z*slat[3][d+2] + r.w*slat[3][d+3];
        }
        const float scC = 0.03608439182435161f;
        sS[0][j] = a0*scC; sS[1][j] = a1*scC; sS[2][j] = a2*scC; sS[3][j] = a3*scC;
    }
    __syncthreads();

    int w = tid >> 5, lane = tid & 31;
    if (w < L_){
        float m = -1e30f;
        for (int j = lane; j < 2*N_; j += 32) m = fmaxf(m, sS[w][j]);
        #pragma unroll
        for (int o = 16; o; o >>= 1) m = fmaxf(m, __shfl_xor_sync(0xffffffffu, m, o));
        float s = 0.f;
        for (int j = lane; j < 2*N_; j += 32){ float e = __expf(sS[w][j] - m); sS[w][j] = e; s += e; }
        #pragma unroll
        for (int o = 16; o; o >>= 1) s += __shfl_xor_sync(0xffffffffu, s, o);
        float inv = 1.f / s;
        for (int j = lane; j < 2*N_; j += 32)
            P[((long)b*L_ + w)*2*N_ + j] = sS[w][j] * inv;
    }
}

// ------- latent fusion: fused[b,l,d] = sum_j P[b,l,j] * concat[b,j,d] --------
__global__ void lat_out(const float* __restrict__ x, const float* __restrict__ y,
                        const float* __restrict__ P, float* __restrict__ fused)
{
    const int b = blockIdx.x;
    const int tid = threadIdx.x;
    __shared__ float sP[L_][2*N_];
    for (int i = tid; i < L_*2*N_; i += 256) ((float*)sP)[i] = P[(long)b*L_*2*N_ + i];
    __syncthreads();

    float acc[L_][3];
    #pragma unroll
    for (int l = 0; l < L_; l++){ acc[l][0]=0.f; acc[l][1]=0.f; acc[l][2]=0.f; }

    for (int j = 0; j < 2*N_; j++){
        const float* row = (j < N_) ? x + ((long)b*N_ + j)*C_
                                    : y + ((long)b*N_ + (j - N_))*C_;
        float r0 = row[tid], r1 = row[tid + 256], r2 = row[tid + 512];
        #pragma unroll
        for (int l = 0; l < L_; l++){
            float p = sP[l][j];
            acc[l][0] += p*r0; acc[l][1] += p*r1; acc[l][2] += p*r2;
        }
    }
    #pragma unroll
    for (int l = 0; l < L_; l++){
        float* o = fused + ((long)b*L_ + l)*C_;
        o[tid] = acc[l][0]; o[tid + 256] = acc[l][1]; o[tid + 512] = acc[l][2];
    }
}

// ------- fuse apply (both streams): out = in + scale * sdpa(in, fused, fused) -
__global__ void fuse_apply2(const float* __restrict__ x, const float* __restrict__ y,
                            const float* __restrict__ fused,
                            const float* __restrict__ scale_a, const float* __restrict__ scale_v,
                            float* __restrict__ outx, float* __restrict__ outy)
{
    const int row = blockIdx.x;              // b*N + n
    const int st  = blockIdx.y;
    const float* in   = st ? y : x;
    const float* scal = st ? scale_v : scale_a;
    float* out = st ? outy : outx;

    const int b = row / N_;
    const float* xr = in + (long)row * C_;
    const float* fb = fused + (long)b * L_ * C_;
    const int tid = threadIdx.x;

    float acc[L_] = {0.f, 0.f, 0.f, 0.f};
    for (int d = tid; d < C_; d += 256){
        float xv = xr[d];
        #pragma unroll
        for (int l = 0; l < L_; l++) acc[l] += xv * fb[l*C_ + d];
    }
    __shared__ float sred[L_][8];
    __shared__ float sp[L_];
    int lane = tid & 31, w = tid >> 5;
    #pragma unroll
    for (int l = 0; l < L_; l++){
        float v = acc[l];
        #pragma unroll
        for (int o = 16; o; o >>= 1) v += __shfl_xor_sync(0xffffffffu, v, o);
        if (lane == 0) sred[l][w] = v;
    }
    __syncthreads();
    if (tid == 0){
        float s[L_]; float m = -1e30f;
        #pragma unroll
        for (int l = 0; l < L_; l++){
            float t = 0.f;
            #pragma unroll
            for (int ww = 0; ww < 8; ww++) t += sred[l][ww];
            t *= 0.03608439182435161f;
            s[l] = t; m = fmaxf(m, t);
        }
        float sum = 0.f;
        #pragma unroll
        for (int l = 0; l < L_; l++){ s[l] = __expf(s[l] - m); sum += s[l]; }
        float inv = 1.f / sum;
        #pragma unroll
        for (int l = 0; l < L_; l++) sp[l] = s[l] * inv;
    }
    __syncthreads();
    float sc = scal[0];
    float p0 = sp[0], p1 = sp[1], p2 = sp[2], p3 = sp[3];
    for (int d = tid; d < C_; d += 256){
        float v = p0*fb[d] + p1*fb[C_ + d] + p2*fb[2*C_ + d] + p3*fb[3*C_ + d];
        out[(long)row*C_ + d] = xr[d] + sc * v;
    }
}

// ---------------- host side ----------------
static inline void gemm128(const float* A, int lda, long sA1, long sA2,
                           const float* Bg, int ldb, long sB1, long sB2, int transB,
                           float* C, int ldc, long sC1, long sC2,
                           const float* bias, long sBias,
                           const float* Res, int ldres, long sR1, long sR2,
                           int M, int N, int K, int batch, int inner, float alpha, int op)
{
    dim3 grid((N + 127) / 128, (M + BM - 1) / BM, batch);
    gemm_tf32_kernel<128,136><<<grid, 256>>>(A, lda, sA1, sA2, Bg, ldb, sB1, sB2, transB,
                                             C, ldc, sC1, sC2, bias, sBias, Res, ldres, sR1, sR2,
                                             M, N, K, inner, alpha, op);
}
static inline void gemm64(const float* A, int lda, long sA1, long sA2,
                          const float* Bg, int ldb, long sB1, long sB2,
                          float* C, int ldc, long sC1, long sC2,
                          int M, int N, int K, int batch, int inner, float alpha)
{
    dim3 grid((N + 63) / 64, (M + BM - 1) / BM, batch);
    gemm_tf32_kernel<64,72><<<grid, 256>>>(A, lda, sA1, sA2, Bg, ldb, sB1, sB2, 0,
                                           C, ldc, sC1, sC2, (const float*)0, 0,
                                           (const float*)0, 0, 0, 0,
                                           M, N, K, inner, alpha, 0);
}

extern "C" void kernel_launch(void* const* d_in, const int* in_sizes, int n_in,
                              void* d_out, int out_size)
{
    const float* x       = (const float*)d_in[0];
    const float* y       = (const float*)d_in[1];
    const float* lat     = (const float*)d_in[2];
    const float* scale_a = (const float*)d_in[3];
    const float* scale_v = (const float*)d_in[4];

    // stream s = d_in[5..16], stream r = d_in[17..28]
    const float* sw[12]; const float* rw[12];
    for (int i = 0; i < 12; i++){ sw[i] = (const float*)d_in[5 + i]; rw[i] = (const float*)d_in[17 + i]; }
    // indices: 0 ln1g 1 ln1b 2 qkvw 3 qkvb 4 projw 5 projb 6 ln2g 7 ln2b 8 fc1w 9 fc1b 10 fc2w 11 fc2b

    float *curx, *lnbuf, *qkvbuf, *attnbuf, *Sbuf, *hid, *fused, *fscore;
    cudaGetSymbolAddress((void**)&curx,   g_cur);
    cudaGetSymbolAddress((void**)&lnbuf,  g_ln);
    cudaGetSymbolAddress((void**)&qkvbuf, g_qkv);
    cudaGetSymbolAddress((void**)&attnbuf,g_attn);
    cudaGetSymbolAddress((void**)&Sbuf,   g_S);
    cudaGetSymbolAddress((void**)&hid,    g_hidden);
    cudaGetSymbolAddress((void**)&fused,  g_fused);
    cudaGetSymbolAddress((void**)&fscore, g_fscore);
    float* cury = curx + BNC_;

    // ---- latent bottleneck fusion ----
    lat_score_softmax<<<B_, 256>>>(x, y, lat, fscore);
    lat_out<<<B_, 256>>>(x, y, fscore, fused);
    fuse_apply2<<<dim3(NT_, 2), 256>>>(x, y, fused, scale_a, scale_v, curx, cury);

    const long QS = (long)NT_ * 3 * C_;     // per-stream qkv stride

    // ---- attn branch, both streams z-merged ----
    ln_kernel<<<NT_, 256>>>(curx, sw[0], sw[1], lnbuf);
    ln_kernel<<<NT_, 256>>>(cury, rw[0], rw[1], lnbuf + BNC_);
    // qkv: z=2 streams, weight/bias via pointer-diff strides
    gemm128(lnbuf, C_, BNC_, 0,
            sw[2], 3*C_, (long)(rw[2] - sw[2]), 0, 0,
            qkvbuf, 3*C_, QS, 0,
            sw[3], (long)(rw[3] - sw[3]), 0, 0, 0, 0,
            NT_, 3*C_, C_, 2, 1, 1.f, 0);
    // S = (Q K^T)/8 : z = st*B*H + b*H + h = zo*H + h with zo in [0,2B)
    gemm128(qkvbuf, 3*C_, (long)N_*3*C_, 64,
            qkvbuf + C_, 3*C_, (long)N_*3*C_, 64, 1,
            Sbuf, N_, (long)H_*N_*N_, (long)N_*N_,
            0, 0, 0, 0, 0, 0,
            N_, N_, 64, 2*B_*H_, H_, 0.125f, 0);
    softmax_rows<<<(2*B_*H_*N_ + 7)/8, 256>>>(Sbuf, 2*B_*H_*N_, N_);
    // O = P V  (BN=64 tiles: no column waste)
    gemm64(Sbuf, N_, (long)H_*N_*N_, (long)N_*N_,
           qkvbuf + 2*C_, 3*C_, (long)N_*3*C_, 64,
           attnbuf, C_, (long)N_*C_, 64,
           N_, 64, N_, 2*B_*H_, H_, 1.f);
    // residual proj
    gemm128(attnbuf, C_, BNC_, 0,
            sw[4], C_, (long)(rw[4] - sw[4]), 0, 0,
            curx, C_, BNC_, 0,
            sw[5], (long)(rw[5] - sw[5]),
            curx, C_, BNC_, 0,
            NT_, C_, C_, 2, 1, 1.f, 0);

    // ---- mlp branch, both streams z-merged ----
    ln_kernel<<<NT_, 256>>>(curx, sw[6], sw[7], lnbuf);
    ln_kernel<<<NT_, 256>>>(cury, rw[6], rw[7], lnbuf + BNC_);
    gemm128(lnbuf, C_, BNC_, 0,
            sw[8], DFF_, (long)(rw[8] - sw[8]), 0, 0,
            hid, DFF_, (long)NT_*DFF_, 0,
            sw[9], (long)(rw[9] - sw[9]), 0, 0, 0, 0,
            NT_, DFF_, C_, 2, 1, 1.f, 1 /*gelu*/);
    gemm128(hid, DFF_, (long)NT_*DFF_, 0,
            sw[10], C_, (long)(rw[10] - sw[10]), 0, 0,
            (float*)d_out, C_, BNC_, 0,
            sw[11], (long)(rw[11] - sw[11]),
            curx, C_, BNC_, 0,
            NT_, C_, DFF_, 2, 1, 1.f, 0);
}

// round 13
// speedup vs baseline: 2.3987x; 1.0234x over previous
#include <cuda_runtime.h>
#include <math.h>

#define B_   32
#define N_   196
#define C_   768
#define H_   12
#define L_   4
#define DFF_ 3072
#define NT_  (B_*N_)        // 6272 tokens
#define BNC_ (NT_*C_)       // 4816896

// ---------------- scratch (stream-major contiguous for z-merged batching) ----
__device__ __align__(256) float g_cur[2*BNC_];
__device__ __align__(256) float g_ln[2*BNC_];
__device__ __align__(256) float g_qkv[2*NT_*3*C_];
__device__ __align__(256) float g_attn[2*BNC_];
__device__ __align__(256) float g_S[2*B_*H_*N_*N_];
__device__ __align__(256) float g_hidden[2*(long)NT_*DFF_];
__device__ __align__(256) float g_fused[B_*L_*C_];
__device__ __align__(256) float g_fscore[B_*L_*2*N_];

// ---------------- mma helper (tf32 operands passed as raw fp32 bits) ----------
__device__ __forceinline__ void mma8(float* d, const unsigned* a, const unsigned* b){
    asm volatile("mma.sync.aligned.m16n8k8.row.col.f32.tf32.tf32.f32 "
        "{%0,%1,%2,%3}, {%4,%5,%6,%7}, {%8,%9}, {%0,%1,%2,%3};\n"
        : "+f"(d[0]), "+f"(d[1]), "+f"(d[2]), "+f"(d[3])
        : "r"(a[0]), "r"(a[1]), "r"(a[2]), "r"(a[3]), "r"(b[0]), "r"(b[1]));
}

// ldmatrix x4: loads the full m16n8k8 tf32 A fragment (a0..a3) in one instruction.
__device__ __forceinline__ void ldsm4(unsigned* r, unsigned addr){
    asm volatile("ldmatrix.sync.aligned.m8n8.x4.shared.b16 {%0,%1,%2,%3}, [%4];\n"
        : "=r"(r[0]), "=r"(r[1]), "=r"(r[2]), "=r"(r[3]) : "r"(addr));
}

// ---------------- cp.async helpers ----------------
__device__ __forceinline__ void cpa16(unsigned dst, const void* src, int bytes){
    asm volatile("cp.async.cg.shared.global [%0], [%1], 16, %2;\n"
                 :: "r"(dst), "l"(src), "r"(bytes));
}
__device__ __forceinline__ void cpcommit(){ asm volatile("cp.async.commit_group;\n"); }
__device__ __forceinline__ void cpwait1(){ asm volatile("cp.async.wait_group 1;\n"); }
__device__ __forceinline__ int clamp4b(int v){ return (v < 0 ? 0 : (v > 4 ? 4 : v)) * 4; }

// ---------------- generic batched GEMM, templated on BN ----------------------
// C = alpha*(A@B) [+bias(+stride)] [gelu] [+Res]. Batch z: zo=z/inner, zi=z%inner.
#define BM  128
#define BKT 16
#define BKP 20
#define ASTG_F (BM*BKP)          // 2560 floats per A stage

template<int BNT, int BNPT>
__global__ void __launch_bounds__(256, 2)
gemm_tf32_kernel(const float* __restrict__ A, int lda, long sA1, long sA2,
                 const float* __restrict__ Bg, int ldb, long sB1, long sB2, int transB,
                 float* __restrict__ C, int ldc, long sC1, long sC2,
                 const float* __restrict__ bias, long sBias,
                 const float* __restrict__ Res, int ldres, long sR1, long sR2,
                 int M, int N, int K, int inner, float alpha, int op)
{
    constexpr int NTC  = BNT / 16;                       // n-tiles per warp
    constexpr int BSTG = (BNT == 128) ? 2560 : (BKT * BNPT);

    __shared__ __align__(16) float As[2][ASTG_F];
    __shared__ __align__(16) float Bs[2][BSTG];

    const int z  = blockIdx.z;
    const int zo = z / inner, zi = z - zo*inner;
    const float* Ab = A  + (long)zo*sA1 + (long)zi*sA2;
    const float* Bb = Bg + (long)zo*sB1 + (long)zi*sB2;
    float*       Cb = C  + (long)zo*sC1 + (long)zi*sC2;
    const float* Rb = Res ? (Res + (long)zo*sR1 + (long)zi*sR2) : (const float*)0;
    const float* biasb = bias ? (bias + (long)zo*sBias) : (const float*)0;

    const int row0 = blockIdx.y * BM;
    const int col0 = blockIdx.x * BNT;
    const int tid  = threadIdx.x;
    const int warp = tid >> 5, lane = tid & 31;
    const int wm = warp >> 1, wn = warp & 1;             // 4x2 warps
    const int g  = lane >> 2, tg = lane & 3;

    float acc[2*NTC][4];
    #pragma unroll
    for (int i = 0; i < 2*NTC; i++){ acc[i][0]=0.f; acc[i][1]=0.f; acc[i][2]=0.f; acc[i][3]=0.f; }

    const int ktiles = (K + BKT - 1) / BKT;

    // ---- per-thread load geometry ----
    const int a_m   = tid >> 1;
    const int a_kk0 = (tid & 1) * 8;
    const bool a_rok = (row0 + a_m) < M;
    const float* a_src = Ab + (long)min(row0 + a_m, M - 1) * lda + a_kk0;
    const unsigned a_dst = (unsigned)__cvta_generic_to_shared(&As[0][a_m*BKP + a_kk0]);

    // ---- ldmatrix A-fragment lane addressing (matrix i <- lanes 8i..8i+7) ----
    // matrix0: rows R..R+7 @k, matrix1: rows R+8..R+15 @k, matrix2/3: same @k+4
    const int lq   = lane >> 3;                 // matrix index this lane feeds
    const int lrow = lane & 7;
    const int am_row = wm*32 + lrow + ((lq & 1) << 3);
    const int am_col = (lq & 2) << 1;           // 0 or 4
    unsigned am_addr[2];
    am_addr[0] = (unsigned)__cvta_generic_to_shared(&As[0][ am_row       *BKP + am_col]);
    am_addr[1] = (unsigned)__cvta_generic_to_shared(&As[0][(am_row + 16)*BKP + am_col]);

    // !transB geometry (BNT=128: 16 rows x 8-float pairs; BNT=64: 16 rows x 4-float)
    const int bn_kk = tid >> 4;
    const int bn_n0 = (BNT == 128) ? (tid & 15) * 8 : (tid & 15) * 4;
    // transB geometry (only BNT=128)
    const int bt_nb  = tid >> 2;
    const int bt_kk0 = (tid & 3) * 4;
    const unsigned b_dst_n = (unsigned)__cvta_generic_to_shared(&Bs[0][bn_kk*BNPT + bn_n0]);
    const unsigned b_dst_t = (unsigned)__cvta_generic_to_shared(&Bs[0][(bt_nb % 64)*BKP + bt_kk0]);
    const unsigned b_dst_t2= (unsigned)__cvta_generic_to_shared(&Bs[0][((bt_nb % 64)+64)*BKP + bt_kk0]);

    auto issueTile = [&](int kt, int s){
        const int k0 = kt * BKT;
        {   // A: two 16B chunks
            int kl = K - (k0 + a_kk0);
            int b0 = a_rok ? clamp4b(kl)     : 0;
            int b1 = a_rok ? clamp4b(kl - 4) : 0;
            unsigned d = a_dst + (unsigned)(s * ASTG_F * 4);
            cpa16(d,      a_src + (b0 ? k0 : 0),     b0);
            cpa16(d + 16, a_src + (b1 ? k0 + 4 : 0), b1);
        }
        if ((BNT == 128) && transB){
            int kk = k0 + bt_kk0;
            int kb = clamp4b(K - kk);
            int gn0 = col0 + bt_nb;
            int gn1 = gn0 + 64;
            int b0 = (gn0 < N) ? kb : 0;
            int b1 = (gn1 < N) ? kb : 0;
            cpa16(b_dst_t  + (unsigned)(s * BSTG * 4),
                  Bb + (long)(b0 ? gn0 : 0)*ldb + (b0 ? kk : 0), b0);
            cpa16(b_dst_t2 + (unsigned)(s * BSTG * 4),
                  Bb + (long)(b1 ? gn1 : 0)*ldb + (b1 ? kk : 0), b1);
        } else {
            int k = k0 + bn_kk;
            bool kok = (k < K);
            long roff = (long)min(k, K - 1) * ldb;
            int cb = col0 + bn_n0;
            unsigned d = b_dst_n + (unsigned)(s * BSTG * 4);
            if (BNT == 128){
                int b0 = kok ? clamp4b(N - cb)     : 0;
                int b1 = kok ? clamp4b(N - cb - 4) : 0;
                cpa16(d,      Bb + roff + (b0 ? cb     : 0), b0);
                cpa16(d + 16, Bb + roff + (b1 ? cb + 4 : 0), b1);
            } else {
                int b0 = kok ? clamp4b(N - cb) : 0;
                cpa16(d, Bb + roff + (b0 ? cb : 0), b0);
            }
        }
    };

    issueTile(0, 0); cpcommit();
    if (ktiles > 1) issueTile(1, 1);
    cpcommit();

    for (int kt = 0; kt < ktiles; kt++){
        const int s = kt & 1;
        cpwait1();
        __syncthreads();

        const unsigned soff = (unsigned)(s * ASTG_F * 4);
        const float* Bsp = Bs[s];
        #pragma unroll
        for (int ks = 0; ks < 2; ks++){
            const int kb = ks * 8;
            unsigned af[2][4];
            #pragma unroll
            for (int mt = 0; mt < 2; mt++)
                ldsm4(af[mt], am_addr[mt] + soff + (unsigned)(kb * 4));
            unsigned bf[NTC][2];
            if ((BNT == 128) && transB){
                #pragma unroll
                for (int nt = 0; nt < NTC; nt++){
                    int c = wn*(BNT/2) + nt*8 + g;
                    bf[nt][0] = __float_as_uint(Bsp[c*BKP + kb + tg    ]);
                    bf[nt][1] = __float_as_uint(Bsp[c*BKP + kb + tg + 4]);
                }
            } else {
                #pragma unroll
                for (int nt = 0; nt < NTC; nt++){
                    int c = wn*(BNT/2) + nt*8 + g;
                    bf[nt][0] = __float_as_uint(Bsp[(kb + tg    )*BNPT + c]);
                    bf[nt][1] = __float_as_uint(Bsp[(kb + tg + 4)*BNPT + c]);
                }
            }
            #pragma unroll
            for (int mt = 0; mt < 2; mt++)
                #pragma unroll
                for (int nt = 0; nt < NTC; nt++)
                    mma8(acc[mt*NTC + nt], af[mt], bf[nt]);
        }

        __syncthreads();
        if (kt + 2 < ktiles) issueTile(kt + 2, s);
        cpcommit();
    }

    // ---------------- epilogue ----------------
    const bool fullTile = (row0 + BM <= M) && (col0 + BNT <= N);
    if (fullTile){
        #pragma unroll
        for (int mt = 0; mt < 2; mt++){
            #pragma unroll
            for (int nt = 0; nt < NTC; nt++){
                const float* a = acc[mt*NTC + nt];
                int rbase = row0 + wm*32 + mt*16 + g;
                int cbase = col0 + wn*(BNT/2) + nt*8 + tg*2;
                float b0 = biasb ? biasb[cbase]     : 0.f;
                float b1 = biasb ? biasb[cbase + 1] : 0.f;
                #pragma unroll
                for (int h = 0; h < 2; h++){
                    int r = rbase + h*8;
                    float v0 = a[h*2]     * alpha + b0;
                    float v1 = a[h*2 + 1] * alpha + b1;
                    if (op == 1){
                        v0 = 0.5f * v0 * (1.0f + erff(v0 * 0.70710678118654752f));
                        v1 = 0.5f * v1 * (1.0f + erff(v1 * 0.70710678118654752f));
                    }
                    if (Rb){
                        v0 += Rb[(long)r*ldres + cbase];
                        v1 += Rb[(long)r*ldres + cbase + 1];
                    }
                    Cb[(long)r*ldc + cbase]     = v0;
                    Cb[(long)r*ldc + cbase + 1] = v1;
                }
            }
        }
    } else {
        #pragma unroll
        for (int mt = 0; mt < 2; mt++){
            #pragma unroll
            for (int nt = 0; nt < NTC; nt++){
                const float* a = acc[mt*NTC + nt];
                int rbase = row0 + wm*32 + mt*16 + g;
                int cbase = col0 + wn*(BNT/2) + nt*8 + tg*2;
                #pragma unroll
                for (int e = 0; e < 4; e++){
                    int r = rbase + (e >> 1) * 8;
                    int c = cbase + (e & 1);
                    if (r < M && c < N){
                        float v = a[e] * alpha;
                        if (biasb) v += biasb[c];
                        if (op == 1) v = 0.5f * v * (1.0f + erff(v * 0.70710678118654752f));
                        if (Rb) v += Rb[(long)r*ldres + c];
                        Cb[(long)r*ldc + c] = v;
                    }
                }
            }
        }
    }
}

// ---------------- LayerNorm: one-pass (sum + sumsq), both streams ------------
__global__ void ln2_kernel(const float* __restrict__ x0, const float* __restrict__ x1,
                           const float* __restrict__ g0, const float* __restrict__ b0,
                           const float* __restrict__ g1, const float* __restrict__ b1,
                           float* __restrict__ out)
{
    const int st  = blockIdx.y;
    const int row = blockIdx.x;
    const float* xr  = (st ? x1 : x0) + (long)row * C_;
    const float* gam = st ? g1 : g0;
    const float* bet = st ? b1 : b0;
    float* orow = out + (long)st * BNC_ + (long)row * C_;
    const int tid = threadIdx.x;

    float v0 = xr[tid], v1 = xr[tid + 256], v2 = xr[tid + 512];
    float s  = v0 + v1 + v2;
    float sq = v0*v0 + v1*v1 + v2*v2;

    __shared__ float sh[8][2];
    __shared__ float tot[2];
    int lane = tid & 31, w = tid >> 5;
    #pragma unroll
    for (int o = 16; o; o >>= 1){
        s  += __shfl_xor_sync(0xffffffffu, s,  o);
        sq += __shfl_xor_sync(0xffffffffu, sq, o);
    }
    if (lane == 0){ sh[w][0] = s; sh[w][1] = sq; }
    __syncthreads();
    if (tid == 0){
        float t0 = 0.f, t1 = 0.f;
        #pragma unroll
        for (int i = 0; i < 8; i++){ t0 += sh[i][0]; t1 += sh[i][1]; }
        tot[0] = t0; tot[1] = t1;
    }
    __syncthreads();
    float mean = tot[0] * (1.f / 768.f);
    float var  = tot[1] * (1.f / 768.f) - mean * mean;
    float rstd = rsqrtf(var + 1e-6f);
    orow[tid      ] = (v0 - mean) * rstd * gam[tid      ] + bet[tid      ];
    orow[tid + 256] = (v1 - mean) * rstd * gam[tid + 256] + bet[tid + 256];
    orow[tid + 512] = (v2 - mean) * rstd * gam[tid + 512] + bet[tid + 512];
}

// ---------------- row softmax (warp per row) ----------------
__global__ void softmax_rows(float* __restrict__ S, int rows, int cols)
{
    int row = blockIdx.x * 8 + (threadIdx.x >> 5);
    if (row >= rows) return;
    int lane = threadIdx.x & 31;
    float* r = S + (long)row * cols;
    float m = -1e30f;
    for (int j = lane; j < cols; j += 32) m = fmaxf(m, r[j]);
    #pragma unroll
    for (int o = 16; o; o >>= 1) m = fmaxf(m, __shfl_xor_sync(0xffffffffu, m, o));
    float s = 0.f;
    for (int j = lane; j < cols; j += 32){ float e = __expf(r[j] - m); r[j] = e; s += e; }
    #pragma unroll
    for (int o = 16; o; o >>= 1) s += __shfl_xor_sync(0xffffffffu, s, o);
    float inv = 1.f / s;
    for (int j = lane; j < cols; j += 32) r[j] *= inv;
}

// ------- latent fusion: P[b,l,:] = softmax( scC * lat[l] . concat[b,j] ) ------
__global__ void lat_score_softmax(const float* __restrict__ x, const float* __restrict__ y,
                                  const float* __restrict__ lat, float* __restrict__ P)
{
    const int b = blockIdx.x;
    const int tid = threadIdx.x;
    __shared__ float slat[L_][C_];
    __shared__ float sS[L_][2*N_];
    for (int i = tid; i < L_*C_; i += 256) ((float*)slat)[i] = lat[i];
    __syncthreads();

    for (int j = tid; j < 2*N_; j += 256){
        const float* row = (j < N_) ? x + ((long)b*N_ + j)*C_
                                    : y + ((long)b*N_ + (j - N_))*C_;
        float a0=0.f, a1=0.f, a2=0.f, a3=0.f;
        for (int d = 0; d < C_; d += 4){
            float4 r = *reinterpret_cast<const float4*>(row + d);
            a0 += r.x*slat[0][d] + r.y*slat[0][d+1] + r.z*slat[0][d+2] + r.w*slat[0][d+3];
            a1 += r.x*slat[1][d] + r.y*slat[1][d+1] + r.z*slat[1][d+2] + r.w*slat[1][d+3];
            a2 += r.x*slat[2][d] + r.y*slat[2][d+1] + r.z*slat[2][d+2] + r.w*slat[2][d+3];
            a3 += r.x*slat[3][d] + r.y*slat[3][d+1] + r.z*slat[3][d+2] + r.w*slat[3][d+3];
        }
        const float scC = 0.03608439182435161f;
        sS[0][j] = a0*scC; sS[1][j] = a1*scC; sS[2][j] = a2*scC; sS[3][j] = a3*scC;
    }
    __syncthreads();

    int w = tid >> 5, lane = tid & 31;
    if (w < L_){
        float m = -1e30f;
        for (int j = lane; j < 2*N_; j += 32) m = fmaxf(m, sS[w][j]);
        #pragma unroll
        for (int o = 16; o; o >>= 1) m = fmaxf(m, __shfl_xor_sync(0xffffffffu, m, o));
        float s = 0.f;
        for (int j = lane; j < 2*N_; j += 32){ float e = __expf(sS[w][j] - m); sS[w][j] = e; s += e; }
        #pragma unroll
        for (int o = 16; o; o >>= 1) s += __shfl_xor_sync(0xffffffffu, s, o);
        float inv = 1.f / s;
        for (int j = lane; j < 2*N_; j += 32)
            P[((long)b*L_ + w)*2*N_ + j] = sS[w][j] * inv;
    }
}

// ------- latent fusion: fused[b,l,d] = sum_j P[b,l,j] * concat[b,j,d] --------
__global__ void lat_out(const float* __restrict__ x, const float* __restrict__ y,
                        const float* __restrict__ P, float* __restrict__ fused)
{
    const int b = blockIdx.x;
    const int tid = threadIdx.x;
    __shared__ float sP[L_][2*N_];
    for (int i = tid; i < L_*2*N_; i += 256) ((float*)sP)[i] = P[(long)b*L_*2*N_ + i];
    __syncthreads();

    float acc[L_][3];
    #pragma unroll
    for (int l = 0; l < L_; l++){ acc[l][0]=0.f; acc[l][1]=0.f; acc[l][2]=0.f; }

    for (int j = 0; j < 2*N_; j++){
        const float* row = (j < N_) ? x + ((long)b*N_ + j)*C_
                                    : y + ((long)b*N_ + (j - N_))*C_;
        float r0 = row[tid], r1 = row[tid + 256], r2 = row[tid + 512];
        #pragma unroll
        for (int l = 0; l < L_; l++){
            float p = sP[l][j];
            acc[l][0] += p*r0; acc[l][1] += p*r1; acc[l][2] += p*r2;
        }
    }
    #pragma unroll
    for (int l = 0; l < L_; l++){
        float* o = fused + ((long)b*L_ + l)*C_;
        o[tid] = acc[l][0]; o[tid + 256] = acc[l][1]; o[tid + 512] = acc[l][2];
    }
}

// ------- fuse apply (both streams): out = in + scale * sdpa(in, fused, fused) -
__global__ void fuse_apply2(const float* __restrict__ x, const float* __restrict__ y,
                            const float* __restrict__ fused,
                            const float* __restrict__ scale_a, const float* __restrict__ scale_v,
                            float* __restrict__ outx, float* __restrict__ outy)
{
    const int row = blockIdx.x;              // b*N + n
    const int st  = blockIdx.y;
    const float* in   = st ? y : x;
    const float* scal = st ? scale_v : scale_a;
    float* out = st ? outy : outx;

    const int b = row / N_;
    const float* xr = in + (long)row * C_;
    const float* fb = fused + (long)b * L_ * C_;
    const int tid = threadIdx.x;

    float acc[L_] = {0.f, 0.f, 0.f, 0.f};
    for (int d = tid; d < C_; d += 256){
        float xv = xr[d];
        #pragma unroll
        for (int l = 0; l < L_; l++) acc[l] += xv * fb[l*C_ + d];
    }
    __shared__ float sred[L_][8];
    __shared__ float sp[L_];
    int lane = tid & 31, w = tid >> 5;
    #pragma unroll
    for (int l = 0; l < L_; l++){
        float v = acc[l];
        #pragma unroll
        for (int o = 16; o; o >>= 1) v += __shfl_xor_sync(0xffffffffu, v, o);
        if (lane == 0) sred[l][w] = v;
    }
    __syncthreads();
    if (tid == 0){
        float s[L_]; float m = -1e30f;
        #pragma unroll
        for (int l = 0; l < L_; l++){
            float t = 0.f;
            #pragma unroll
            for (int ww = 0; ww < 8; ww++) t += sred[l][ww];
            t *= 0.03608439182435161f;
            s[l] = t; m = fmaxf(m, t);
        }
        float sum = 0.f;
        #pragma unroll
        for (int l = 0; l < L_; l++){ s[l] = __expf(s[l] - m); sum += s[l]; }
        float inv = 1.f / sum;
        #pragma unroll
        for (int l = 0; l < L_; l++) sp[l] = s[l] * inv;
    }
    __syncthreads();
    float sc = scal[0];
    float p0 = sp[0], p1 = sp[1], p2 = sp[2], p3 = sp[3];
    for (int d = tid; d < C_; d += 256){
        float v = p0*fb[d] + p1*fb[C_ + d] + p2*fb[2*C_ + d] + p3*fb[3*C_ + d];
        out[(long)row*C_ + d] = xr[d] + sc * v;
    }
}

// ---------------- host side ----------------
static inline void gemm128(const float* A, int lda, long sA1, long sA2,
                           const float* Bg, int ldb, long sB1, long sB2, int transB,
                           float* C, int ldc, long sC1, long sC2,
                           const float* bias, long sBias,
                           const float* Res, int ldres, long sR1, long sR2,
                           int M, int N, int K, int batch, int inner, float alpha, int op)
{
    dim3 grid((N + 127) / 128, (M + BM - 1) / BM, batch);
    gemm_tf32_kernel<128,136><<<grid, 256>>>(A, lda, sA1, sA2, Bg, ldb, sB1, sB2, transB,
                                             C, ldc, sC1, sC2, bias, sBias, Res, ldres, sR1, sR2,
                                             M, N, K, inner, alpha, op);
}
static inline void gemm64(const float* A, int lda, long sA1, long sA2,
                          const float* Bg, int ldb, long sB1, long sB2,
                          float* C, int ldc, long sC1, long sC2,
                          int M, int N, int K, int batch, int inner, float alpha)
{
    dim3 grid((N + 63) / 64, (M + BM - 1) / BM, batch);
    gemm_tf32_kernel<64,72><<<grid, 256>>>(A, lda, sA1, sA2, Bg, ldb, sB1, sB2, 0,
                                           C, ldc, sC1, sC2, (const float*)0, 0,
                                           (const float*)0, 0, 0, 0,
                                           M, N, K, inner, alpha, 0);
}

extern "C" void kernel_launch(void* const* d_in, const int* in_sizes, int n_in,
                              void* d_out, int out_size)
{
    const float* x       = (const float*)d_in[0];
    const float* y       = (const float*)d_in[1];
    const float* lat     = (const float*)d_in[2];
    const float* scale_a = (const float*)d_in[3];
    const float* scale_v = (const float*)d_in[4];

    // stream s = d_in[5..16], stream r = d_in[17..28]
    const float* sw[12]; const float* rw[12];
    for (int i = 0; i < 12; i++){ sw[i] = (const float*)d_in[5 + i]; rw[i] = (const float*)d_in[17 + i]; }
    // indices: 0 ln1g 1 ln1b 2 qkvw 3 qkvb 4 projw 5 projb 6 ln2g 7 ln2b 8 fc1w 9 fc1b 10 fc2w 11 fc2b

    float *curx, *lnbuf, *qkvbuf, *attnbuf, *Sbuf, *hid, *fused, *fscore;
    cudaGetSymbolAddress((void**)&curx,   g_cur);
    cudaGetSymbolAddress((void**)&lnbuf,  g_ln);
    cudaGetSymbolAddress((void**)&qkvbuf, g_qkv);
    cudaGetSymbolAddress((void**)&attnbuf,g_attn);
    cudaGetSymbolAddress((void**)&Sbuf,   g_S);
    cudaGetSymbolAddress((void**)&hid,    g_hidden);
    cudaGetSymbolAddress((void**)&fused,  g_fused);
    cudaGetSymbolAddress((void**)&fscore, g_fscore);
    float* cury = curx + BNC_;

    // ---- latent bottleneck fusion ----
    lat_score_softmax<<<B_, 256>>>(x, y, lat, fscore);
    lat_out<<<B_, 256>>>(x, y, fscore, fused);
    fuse_apply2<<<dim3(NT_, 2), 256>>>(x, y, fused, scale_a, scale_v, curx, cury);

    const long QS = (long)NT_ * 3 * C_;     // per-stream qkv stride

    // ---- attn branch, both streams z-merged ----
    ln2_kernel<<<dim3(NT_, 2), 256>>>(curx, cury, sw[0], sw[1], rw[0], rw[1], lnbuf);
    // qkv: z=2 streams, weight/bias via pointer-diff strides
    gemm128(lnbuf, C_, BNC_, 0,
            sw[2], 3*C_, (long)(rw[2] - sw[2]), 0, 0,
            qkvbuf, 3*C_, QS, 0,
            sw[3], (long)(rw[3] - sw[3]), 0, 0, 0, 0,
            NT_, 3*C_, C_, 2, 1, 1.f, 0);
    // S = (Q K^T)/8 : z = st*B*H + b*H + h = zo*H + h with zo in [0,2B)
    gemm128(qkvbuf, 3*C_, (long)N_*3*C_, 64,
            qkvbuf + C_, 3*C_, (long)N_*3*C_, 64, 1,
            Sbuf, N_, (long)H_*N_*N_, (long)N_*N_,
            0, 0, 0, 0, 0, 0,
            N_, N_, 64, 2*B_*H_, H_, 0.125f, 0);
    softmax_rows<<<(2*B_*H_*N_ + 7)/8, 256>>>(Sbuf, 2*B_*H_*N_, N_);
    // O = P V  (BN=64 tiles: no column waste)
    gemm64(Sbuf, N_, (long)H_*N_*N_, (long)N_*N_,
           qkvbuf + 2*C_, 3*C_, (long)N_*3*C_, 64,
           attnbuf, C_, (long)N_*C_, 64,
           N_, 64, N_, 2*B_*H_, H_, 1.f);
    // residual proj
    gemm128(attnbuf, C_, BNC_, 0,
            sw[4], C_, (long)(rw[4] - sw[4]), 0, 0,
            curx, C_, BNC_, 0,
            sw[5], (long)(rw[5] - sw[5]),
            curx, C_, BNC_, 0,
            NT_, C_, C_, 2, 1, 1.f, 0);

    // ---- mlp branch, both streams z-merged ----
    ln2_kernel<<<dim3(NT_, 2), 256>>>(curx, cury, sw[6], sw[7], rw[6], rw[7], lnbuf);
    gemm128(lnbuf, C_, BNC_, 0,
            sw[8], DFF_, (long)(rw[8] - sw[8]), 0, 0,
            hid, DFF_, (long)NT_*DFF_, 0,
            sw[9], (long)(rw[9] - sw[9]), 0, 0, 0, 0,
            NT_, DFF_, C_, 2, 1, 1.f, 1 /*gelu*/);
    gemm128(hid, DFF_, (long)NT_*DFF_, 0,
            sw[10], C_, (long)(rw[10] - sw[10]), 0, 0,
            (float*)d_out, C_, BNC_, 0,
            sw[11], (long)(rw[11] - sw[11]),
            curx, C_, BNC_, 0,
            NT_, C_, DFF_, 2, 1, 1.f, 0);
}